// round 1
// baseline (speedup 1.0000x reference)
#include <cuda_runtime.h>

// Problem constants
#define B_  4
#define S_  2048
#define D_  1024
#define H_  16
#define DK_ 64
#define M_  (B_ * S_)   // 8192 rows

// Scratch (device globals — no allocation allowed in kernel_launch)
__device__ float g_Q [B_ * H_ * S_ * DK_];   // [b,h,s,k]
__device__ float g_K [B_ * H_ * S_ * DK_];
__device__ float g_V [B_ * H_ * S_ * DK_];
__device__ float g_Hd[M_ * D_];              // concat heads [b,s,h*64+v]

// ---------------------------------------------------------------------------
// Projection GEMM: out[b,h,s,kk] = sum_d X[b*s, d] * W[h, d, kk]
// M=8192, N=1024 (col = h*64+kk), K=1024. BM=BN=64, BK=16, 256 threads, 4x4/thread.
// Column tile (64) aligns exactly with one head, so h = blockIdx.x.
// which: 0 -> g_Q, 1 -> g_K, 2 -> g_V
// ---------------------------------------------------------------------------
__global__ __launch_bounds__(256) void proj_gemm(const float* __restrict__ X,
                                                 const float* __restrict__ W,
                                                 int which)
{
    __shared__ float As[16][64];   // [k][m]
    __shared__ float Bs[16][64];   // [k][n]

    float* out = (which == 0) ? g_Q : ((which == 1) ? g_K : g_V);

    const int tid = threadIdx.x;
    const int tx  = tid & 15;
    const int ty  = tid >> 4;
    const int h   = blockIdx.x;          // head (== n0/64)
    const int m0  = blockIdx.y * 64;

    const int arow = tid >> 2;           // 0..63
    const int acol = (tid & 3) * 4;      // 0,4,8,12
    const int brow = tid >> 4;           // 0..15
    const int bcol = (tid & 15) * 4;     // 0..60

    float acc[4][4] = {};

    for (int k0 = 0; k0 < D_; k0 += 16) {
        float4 av = *reinterpret_cast<const float4*>(&X[(m0 + arow) * D_ + k0 + acol]);
        As[acol + 0][arow] = av.x;
        As[acol + 1][arow] = av.y;
        As[acol + 2][arow] = av.z;
        As[acol + 3][arow] = av.w;
        float4 bv = *reinterpret_cast<const float4*>(&W[(h * D_ + k0 + brow) * 64 + bcol]);
        *reinterpret_cast<float4*>(&Bs[brow][bcol]) = bv;
        __syncthreads();

        #pragma unroll
        for (int k = 0; k < 16; ++k) {
            float4 a = *reinterpret_cast<const float4*>(&As[k][ty * 4]);
            float4 b = *reinterpret_cast<const float4*>(&Bs[k][tx * 4]);
            float ar[4] = {a.x, a.y, a.z, a.w};
            float br[4] = {b.x, b.y, b.z, b.w};
            #pragma unroll
            for (int i = 0; i < 4; ++i)
                #pragma unroll
                for (int j = 0; j < 4; ++j)
                    acc[i][j] = fmaf(ar[i], br[j], acc[i][j]);
        }
        __syncthreads();
    }

    #pragma unroll
    for (int i = 0; i < 4; ++i) {
        int m = m0 + ty * 4 + i;
        int b = m >> 11;               // m / S_
        int s = m & (S_ - 1);
        float4 o = make_float4(acc[i][0], acc[i][1], acc[i][2], acc[i][3]);
        *reinterpret_cast<float4*>(&out[((b * H_ + h) * S_ + s) * 64 + tx * 4]) = o;
    }
}

// ---------------------------------------------------------------------------
// Output GEMM: out[m, n] = sum_k g_Hd[m, k] * Wo[k, n]   (M=8192, N=K=1024)
// ---------------------------------------------------------------------------
__global__ __launch_bounds__(256) void out_gemm(const float* __restrict__ Wo,
                                                float* __restrict__ out)
{
    __shared__ float As[16][64];
    __shared__ float Bs[16][64];

    const int tid = threadIdx.x;
    const int tx  = tid & 15;
    const int ty  = tid >> 4;
    const int n0  = blockIdx.x * 64;
    const int m0  = blockIdx.y * 64;

    const int arow = tid >> 2;
    const int acol = (tid & 3) * 4;
    const int brow = tid >> 4;
    const int bcol = (tid & 15) * 4;

    float acc[4][4] = {};

    for (int k0 = 0; k0 < D_; k0 += 16) {
        float4 av = *reinterpret_cast<const float4*>(&g_Hd[(m0 + arow) * D_ + k0 + acol]);
        As[acol + 0][arow] = av.x;
        As[acol + 1][arow] = av.y;
        As[acol + 2][arow] = av.z;
        As[acol + 3][arow] = av.w;
        float4 bv = *reinterpret_cast<const float4*>(&Wo[(k0 + brow) * D_ + n0 + bcol]);
        *reinterpret_cast<float4*>(&Bs[brow][bcol]) = bv;
        __syncthreads();

        #pragma unroll
        for (int k = 0; k < 16; ++k) {
            float4 a = *reinterpret_cast<const float4*>(&As[k][ty * 4]);
            float4 b = *reinterpret_cast<const float4*>(&Bs[k][tx * 4]);
            float ar[4] = {a.x, a.y, a.z, a.w};
            float br[4] = {b.x, b.y, b.z, b.w};
            #pragma unroll
            for (int i = 0; i < 4; ++i)
                #pragma unroll
                for (int j = 0; j < 4; ++j)
                    acc[i][j] = fmaf(ar[i], br[j], acc[i][j]);
        }
        __syncthreads();
    }

    #pragma unroll
    for (int i = 0; i < 4; ++i) {
        int m = m0 + ty * 4 + i;
        float4 o = make_float4(acc[i][0], acc[i][1], acc[i][2], acc[i][3]);
        *reinterpret_cast<float4*>(&out[m * D_ + n0 + tx * 4]) = o;
    }
}

// ---------------------------------------------------------------------------
// Flash attention (fp32, online softmax). One query row per thread.
// grid = (S/128, B*H), block = 128 threads.
// Each block: 128 query rows of one (b,h); loops over K/V in 32-row tiles.
// q[64] and acc[64] live in registers; score row staged in padded smem.
// Writes concat-head layout g_Hd[b, s, h*64 + v].
// ---------------------------------------------------------------------------
__global__ __launch_bounds__(128) void attn_kernel()
{
    __shared__ float Ks[32][64];
    __shared__ float Vs[32][64];
    __shared__ float Sbuf[128][33];   // stride 33 -> conflict-free per-thread rows

    const int tid  = threadIdx.x;
    const int bh   = blockIdx.y;                 // b*16 + h
    const int srow = blockIdx.x * 128 + tid;

    const float* Qr = &g_Q[(bh * S_ + srow) * 64];
    float q[64];
    #pragma unroll
    for (int d = 0; d < 64; ++d) q[d] = Qr[d] * 0.125f;   // pre-scale by 1/sqrt(64)

    float acc[64];
    #pragma unroll
    for (int d = 0; d < 64; ++d) acc[d] = 0.0f;
    float mmax = -1e30f;
    float lsum = 0.0f;

    const float* Kbase = &g_K[bh * S_ * 64];
    const float* Vbase = &g_V[bh * S_ * 64];

    for (int kt = 0; kt < S_; kt += 32) {
        // Cooperative load: 32x64 floats each for K and V (4 float4 per thread each)
        #pragma unroll
        for (int i = 0; i < 4; ++i) {
            int f = tid * 4 + i;          // 0..511
            int r = f >> 4;               // 0..31
            int c = (f & 15) * 4;         // 0..60
            *reinterpret_cast<float4*>(&Ks[r][c]) =
                *reinterpret_cast<const float4*>(&Kbase[(kt + r) * 64 + c]);
            *reinterpret_cast<float4*>(&Vs[r][c]) =
                *reinterpret_cast<const float4*>(&Vbase[(kt + r) * 64 + c]);
        }
        __syncthreads();

        // Scores for this tile, tracking tile max
        float tmax = -1e30f;
        #pragma unroll 4
        for (int j = 0; j < 32; ++j) {
            float px = 0.f, py = 0.f, pz = 0.f, pw = 0.f;
            #pragma unroll
            for (int d4 = 0; d4 < 16; ++d4) {
                float4 kv = *reinterpret_cast<const float4*>(&Ks[j][d4 * 4]);
                px = fmaf(q[d4 * 4 + 0], kv.x, px);
                py = fmaf(q[d4 * 4 + 1], kv.y, py);
                pz = fmaf(q[d4 * 4 + 2], kv.z, pz);
                pw = fmaf(q[d4 * 4 + 3], kv.w, pw);
            }
            float s = (px + py) + (pz + pw);
            Sbuf[tid][j] = s;
            tmax = fmaxf(tmax, s);
        }

        float mnew = fmaxf(mmax, tmax);
        if (mnew > mmax) {
            float corr = __expf(mmax - mnew);
            lsum *= corr;
            #pragma unroll
            for (int d = 0; d < 64; ++d) acc[d] *= corr;
            mmax = mnew;
        }

        // exp + P@V accumulate
        #pragma unroll 2
        for (int j = 0; j < 32; ++j) {
            float p = __expf(Sbuf[tid][j] - mmax);
            lsum += p;
            #pragma unroll
            for (int d4 = 0; d4 < 16; ++d4) {
                float4 vv = *reinterpret_cast<const float4*>(&Vs[j][d4 * 4]);
                acc[d4 * 4 + 0] = fmaf(p, vv.x, acc[d4 * 4 + 0]);
                acc[d4 * 4 + 1] = fmaf(p, vv.y, acc[d4 * 4 + 1]);
                acc[d4 * 4 + 2] = fmaf(p, vv.z, acc[d4 * 4 + 2]);
                acc[d4 * 4 + 3] = fmaf(p, vv.w, acc[d4 * 4 + 3]);
            }
        }
        __syncthreads();
    }

    const float inv = 1.0f / lsum;
    const int b = bh >> 4;
    const int h = bh & 15;
    float* outp = &g_Hd[(b * S_ + srow) * D_ + h * 64];
    #pragma unroll
    for (int d4 = 0; d4 < 16; ++d4) {
        float4 o = make_float4(acc[d4 * 4 + 0] * inv, acc[d4 * 4 + 1] * inv,
                               acc[d4 * 4 + 2] * inv, acc[d4 * 4 + 3] * inv);
        *reinterpret_cast<float4*>(&outp[d4 * 4]) = o;
    }
}

// ---------------------------------------------------------------------------
// Launch
// ---------------------------------------------------------------------------
extern "C" void kernel_launch(void* const* d_in, const int* in_sizes, int n_in,
                              void* d_out, int out_size)
{
    const float* q  = (const float*)d_in[0];
    const float* k  = (const float*)d_in[1];
    const float* v  = (const float*)d_in[2];
    const float* Wq = (const float*)d_in[3];
    const float* Wk = (const float*)d_in[4];
    const float* Wv = (const float*)d_in[5];
    const float* Wo = (const float*)d_in[6];
    float* out = (float*)d_out;

    dim3 gemm_grid(H_, M_ / 64);          // 16 x 128
    proj_gemm<<<gemm_grid, 256>>>(q, Wq, 0);
    proj_gemm<<<gemm_grid, 256>>>(k, Wk, 1);
    proj_gemm<<<gemm_grid, 256>>>(v, Wv, 2);

    dim3 attn_grid(S_ / 128, B_ * H_);    // 16 x 64
    attn_kernel<<<attn_grid, 128>>>();

    dim3 out_grid(D_ / 64, M_ / 64);      // 16 x 128
    out_gemm<<<out_grid, 256>>>(Wo, out);
}

// round 2
// speedup vs baseline: 1.2447x; 1.2447x over previous
#include <cuda_runtime.h>

#define B_  4
#define S_  2048
#define D_  1024
#define H_  16

// Scratch device globals (no allocation allowed)
__device__ float g_Q [B_ * H_ * S_ * 64];   // [bh][s][dk]
__device__ float g_K [B_ * H_ * S_ * 64];
__device__ float g_V [B_ * H_ * S_ * 64];
__device__ float g_Hd[B_ * S_ * D_];        // concat heads [b,s,h*64+v]

// ---------------------------------------------------------------------------
// Projection GEMM: 128x64 tile, 128 threads, 8x8 microtile.
// out[bh][s][kk] = sum_d X[m,d] * W[h,d,kk];  one head per blockIdx.x.
// which: 0->g_Q 1->g_K 2->g_V
// ---------------------------------------------------------------------------
__global__ __launch_bounds__(128) void proj_gemm(const float* __restrict__ X,
                                                 const float* __restrict__ W,
                                                 int which)
{
    __shared__ float As[16][128];   // [k][m]
    __shared__ float Bs[16][64];    // [k][n]

    float* out = (which == 0) ? g_Q : ((which == 1) ? g_K : g_V);

    const int tid = threadIdx.x;
    const int tx  = tid & 7;        // n-group (8 cols)
    const int ty  = tid >> 3;       // m-group (8 rows), 0..15
    const int h   = blockIdx.x;
    const int m0  = blockIdx.y * 128;

    float acc[8][8] = {};

    for (int k0 = 0; k0 < D_; k0 += 16) {
        // A: 128 rows x 16 k. Thread tid loads row (m0+tid), 4 float4.
        #pragma unroll
        for (int i = 0; i < 4; ++i) {
            float4 a = *reinterpret_cast<const float4*>(&X[(m0 + tid) * D_ + k0 + i * 4]);
            As[i * 4 + 0][tid] = a.x;
            As[i * 4 + 1][tid] = a.y;
            As[i * 4 + 2][tid] = a.z;
            As[i * 4 + 3][tid] = a.w;
        }
        // B: 16 x 64, direct copy (2 float4 per thread)
        #pragma unroll
        for (int i = 0; i < 2; ++i) {
            int idx = i * 128 + tid;          // 0..255 float4 units
            int kr  = idx >> 4;
            int nc  = (idx & 15) * 4;
            *reinterpret_cast<float4*>(&Bs[kr][nc]) =
                *reinterpret_cast<const float4*>(&W[(h * D_ + k0 + kr) * 64 + nc]);
        }
        __syncthreads();

        #pragma unroll
        for (int k = 0; k < 16; ++k) {
            float a[8], b[8];
            *reinterpret_cast<float4*>(&a[0]) = *reinterpret_cast<const float4*>(&As[k][ty * 8]);
            *reinterpret_cast<float4*>(&a[4]) = *reinterpret_cast<const float4*>(&As[k][ty * 8 + 4]);
            *reinterpret_cast<float4*>(&b[0]) = *reinterpret_cast<const float4*>(&Bs[k][tx * 8]);
            *reinterpret_cast<float4*>(&b[4]) = *reinterpret_cast<const float4*>(&Bs[k][tx * 8 + 4]);
            #pragma unroll
            for (int i = 0; i < 8; ++i)
                #pragma unroll
                for (int j = 0; j < 8; ++j)
                    acc[i][j] = fmaf(a[i], b[j], acc[i][j]);
        }
        __syncthreads();
    }

    #pragma unroll
    for (int i = 0; i < 8; ++i) {
        int m = m0 + ty * 8 + i;
        int b = m >> 11;
        int s = m & (S_ - 1);
        float* o = &out[((b * H_ + h) * S_ + s) * 64 + tx * 8];
        *reinterpret_cast<float4*>(&o[0]) = make_float4(acc[i][0], acc[i][1], acc[i][2], acc[i][3]);
        *reinterpret_cast<float4*>(&o[4]) = make_float4(acc[i][4], acc[i][5], acc[i][6], acc[i][7]);
    }
}

// ---------------------------------------------------------------------------
// Output GEMM: out[m,n] = sum_k g_Hd[m,k] * Wo[k,n]. Same 128x64 / 8x8 scheme.
// ---------------------------------------------------------------------------
__global__ __launch_bounds__(128) void out_gemm(const float* __restrict__ Wo,
                                                float* __restrict__ out)
{
    __shared__ float As[16][128];
    __shared__ float Bs[16][64];

    const int tid = threadIdx.x;
    const int tx  = tid & 7;
    const int ty  = tid >> 3;
    const int n0  = blockIdx.x * 64;
    const int m0  = blockIdx.y * 128;

    float acc[8][8] = {};

    for (int k0 = 0; k0 < D_; k0 += 16) {
        #pragma unroll
        for (int i = 0; i < 4; ++i) {
            float4 a = *reinterpret_cast<const float4*>(&g_Hd[(m0 + tid) * D_ + k0 + i * 4]);
            As[i * 4 + 0][tid] = a.x;
            As[i * 4 + 1][tid] = a.y;
            As[i * 4 + 2][tid] = a.z;
            As[i * 4 + 3][tid] = a.w;
        }
        #pragma unroll
        for (int i = 0; i < 2; ++i) {
            int idx = i * 128 + tid;
            int kr  = idx >> 4;
            int nc  = (idx & 15) * 4;
            *reinterpret_cast<float4*>(&Bs[kr][nc]) =
                *reinterpret_cast<const float4*>(&Wo[(k0 + kr) * D_ + n0 + nc]);
        }
        __syncthreads();

        #pragma unroll
        for (int k = 0; k < 16; ++k) {
            float a[8], b[8];
            *reinterpret_cast<float4*>(&a[0]) = *reinterpret_cast<const float4*>(&As[k][ty * 8]);
            *reinterpret_cast<float4*>(&a[4]) = *reinterpret_cast<const float4*>(&As[k][ty * 8 + 4]);
            *reinterpret_cast<float4*>(&b[0]) = *reinterpret_cast<const float4*>(&Bs[k][tx * 8]);
            *reinterpret_cast<float4*>(&b[4]) = *reinterpret_cast<const float4*>(&Bs[k][tx * 8 + 4]);
            #pragma unroll
            for (int i = 0; i < 8; ++i)
                #pragma unroll
                for (int j = 0; j < 8; ++j)
                    acc[i][j] = fmaf(a[i], b[j], acc[i][j]);
        }
        __syncthreads();
    }

    #pragma unroll
    for (int i = 0; i < 8; ++i) {
        int m = m0 + ty * 8 + i;
        float* o = &out[m * D_ + n0 + tx * 8];
        *reinterpret_cast<float4*>(&o[0]) = make_float4(acc[i][0], acc[i][1], acc[i][2], acc[i][3]);
        *reinterpret_cast<float4*>(&o[4]) = make_float4(acc[i][4], acc[i][5], acc[i][6], acc[i][7]);
    }
}

// ---------------------------------------------------------------------------
// Flash attention, register-tiled. Block: 128 q rows x 64-key tiles,
// 128 threads, 8x8 microtiles for both QK^T and PV.
// Dynamic smem layout (floats):
//   Qs [64][128]  (d-major)   offset 0      (8192)
//   Ks [64][64]   (d-major)   offset 8192   (4096)
//   Vs [64][64]   (k-major)   offset 12288  (4096)
//   Ps [128][68]  (q-major)   offset 16384  (8704)
// total 25088 floats = 100352 bytes
// ---------------------------------------------------------------------------
#define PS_PAD 68

__global__ __launch_bounds__(128) void attn_kernel()
{
    extern __shared__ float sm[];
    float* Qs = sm;            // [d][q]   d*128+q
    float* Ks = sm + 8192;     // [d][k]   d*64+k
    float* Vs = sm + 12288;    // [k][dv]  k*64+dv
    float* Ps = sm + 16384;    // [q][kk]  q*PS_PAD+kk

    const int tid = threadIdx.x;
    const int tx  = tid & 7;       // key-group / dv-group
    const int ty  = tid >> 3;      // q-group, 0..15
    const int bh  = blockIdx.y;
    const int q0  = blockIdx.x * 128;

    // Load Q tile (transpose to [d][q], pre-scaled by 1/sqrt(64))
    {
        const float* Qg = &g_Q[(bh * S_ + q0) * 64];
        #pragma unroll
        for (int i = 0; i < 16; ++i) {
            int idx = i * 128 + tid;       // 0..2047 float4 units
            int r   = idx >> 4;            // q row 0..127
            int c   = (idx & 15) * 4;      // d col
            float4 qv = *reinterpret_cast<const float4*>(&Qg[r * 64 + c]);
            Qs[(c + 0) * 128 + r] = qv.x * 0.125f;
            Qs[(c + 1) * 128 + r] = qv.y * 0.125f;
            Qs[(c + 2) * 128 + r] = qv.z * 0.125f;
            Qs[(c + 3) * 128 + r] = qv.w * 0.125f;
        }
    }

    float O[8][8] = {};
    float mrow[8], lrow[8];
    #pragma unroll
    for (int i = 0; i < 8; ++i) { mrow[i] = -1e30f; lrow[i] = 0.0f; }

    const float* Kbase = &g_K[bh * S_ * 64];
    const float* Vbase = &g_V[bh * S_ * 64];

    for (int kt = 0; kt < S_; kt += 64) {
        // Load K tile (transpose -> [d][k]) and V tile (direct [k][dv])
        #pragma unroll
        for (int i = 0; i < 8; ++i) {
            int idx = i * 128 + tid;      // 0..1023 float4 units
            int r   = idx >> 4;           // key row 0..63
            int c   = (idx & 15) * 4;     // d col
            float4 kv = *reinterpret_cast<const float4*>(&Kbase[(kt + r) * 64 + c]);
            Ks[(c + 0) * 64 + r] = kv.x;
            Ks[(c + 1) * 64 + r] = kv.y;
            Ks[(c + 2) * 64 + r] = kv.z;
            Ks[(c + 3) * 64 + r] = kv.w;
            *reinterpret_cast<float4*>(&Vs[r * 64 + c]) =
                *reinterpret_cast<const float4*>(&Vbase[(kt + r) * 64 + c]);
        }
        __syncthreads();

        // QK^T: s[i][j], q rows = q0+ty*8+i, keys = kt+tx*8+j
        float s[8][8] = {};
        #pragma unroll
        for (int d = 0; d < 64; ++d) {
            float a[8], b[8];
            *reinterpret_cast<float4*>(&a[0]) = *reinterpret_cast<const float4*>(&Qs[d * 128 + ty * 8]);
            *reinterpret_cast<float4*>(&a[4]) = *reinterpret_cast<const float4*>(&Qs[d * 128 + ty * 8 + 4]);
            *reinterpret_cast<float4*>(&b[0]) = *reinterpret_cast<const float4*>(&Ks[d * 64 + tx * 8]);
            *reinterpret_cast<float4*>(&b[4]) = *reinterpret_cast<const float4*>(&Ks[d * 64 + tx * 8 + 4]);
            #pragma unroll
            for (int i = 0; i < 8; ++i)
                #pragma unroll
                for (int j = 0; j < 8; ++j)
                    s[i][j] = fmaf(a[i], b[j], s[i][j]);
        }

        // Online softmax. 8 lanes (tx) share each q row -> shuffle reduce.
        #pragma unroll
        for (int i = 0; i < 8; ++i) {
            float tm = s[i][0];
            #pragma unroll
            for (int j = 1; j < 8; ++j) tm = fmaxf(tm, s[i][j]);
            tm = fmaxf(tm, __shfl_xor_sync(0xffffffffu, tm, 1));
            tm = fmaxf(tm, __shfl_xor_sync(0xffffffffu, tm, 2));
            tm = fmaxf(tm, __shfl_xor_sync(0xffffffffu, tm, 4));

            float mnew = fmaxf(mrow[i], tm);
            float corr = __expf(mrow[i] - mnew);
            mrow[i] = mnew;

            float rsum = 0.0f;
            float p[8];
            #pragma unroll
            for (int j = 0; j < 8; ++j) {
                p[j] = __expf(s[i][j] - mnew);
                rsum += p[j];
            }
            rsum += __shfl_xor_sync(0xffffffffu, rsum, 1);
            rsum += __shfl_xor_sync(0xffffffffu, rsum, 2);
            rsum += __shfl_xor_sync(0xffffffffu, rsum, 4);
            lrow[i] = lrow[i] * corr + rsum;

            #pragma unroll
            for (int c = 0; c < 8; ++c) O[i][c] *= corr;

            // store P row chunk: Ps[q][kk]
            float* pr = &Ps[(ty * 8 + i) * PS_PAD + tx * 8];
            *reinterpret_cast<float4*>(&pr[0]) = make_float4(p[0], p[1], p[2], p[3]);
            *reinterpret_cast<float4*>(&pr[4]) = make_float4(p[4], p[5], p[6], p[7]);
        }
        __syncthreads();

        // PV: O[i][c] += sum_kk P[q][kk] * Vs[kk][tx*8+c]
        #pragma unroll 8
        for (int kk = 0; kk < 64; ++kk) {
            float b[8];
            *reinterpret_cast<float4*>(&b[0]) = *reinterpret_cast<const float4*>(&Vs[kk * 64 + tx * 8]);
            *reinterpret_cast<float4*>(&b[4]) = *reinterpret_cast<const float4*>(&Vs[kk * 64 + tx * 8 + 4]);
            #pragma unroll
            for (int i = 0; i < 8; ++i) {
                float pa = Ps[(ty * 8 + i) * PS_PAD + kk];
                #pragma unroll
                for (int c = 0; c < 8; ++c)
                    O[i][c] = fmaf(pa, b[c], O[i][c]);
            }
        }
        __syncthreads();
    }

    // Epilogue: normalize, write concat-head layout
    const int b = bh >> 4;
    const int h = bh & 15;
    #pragma unroll
    for (int i = 0; i < 8; ++i) {
        float inv = 1.0f / lrow[i];
        int srow  = q0 + ty * 8 + i;
        float* o  = &g_Hd[(b * S_ + srow) * D_ + h * 64 + tx * 8];
        *reinterpret_cast<float4*>(&o[0]) =
            make_float4(O[i][0] * inv, O[i][1] * inv, O[i][2] * inv, O[i][3] * inv);
        *reinterpret_cast<float4*>(&o[4]) =
            make_float4(O[i][4] * inv, O[i][5] * inv, O[i][6] * inv, O[i][7] * inv);
    }
}

// ---------------------------------------------------------------------------
// Launch
// ---------------------------------------------------------------------------
extern "C" void kernel_launch(void* const* d_in, const int* in_sizes, int n_in,
                              void* d_out, int out_size)
{
    const float* q  = (const float*)d_in[0];
    const float* k  = (const float*)d_in[1];
    const float* v  = (const float*)d_in[2];
    const float* Wq = (const float*)d_in[3];
    const float* Wk = (const float*)d_in[4];
    const float* Wv = (const float*)d_in[5];
    const float* Wo = (const float*)d_in[6];
    float* out = (float*)d_out;

    static bool configured = false;
    if (!configured) {
        cudaFuncSetAttribute(attn_kernel, cudaFuncAttributeMaxDynamicSharedMemorySize,
                             25088 * (int)sizeof(float));
        configured = true;
    }

    dim3 proj_grid(H_, 8192 / 128);       // 16 x 64
    proj_gemm<<<proj_grid, 128>>>(q, Wq, 0);
    proj_gemm<<<proj_grid, 128>>>(k, Wk, 1);
    proj_gemm<<<proj_grid, 128>>>(v, Wv, 2);

    dim3 attn_grid(S_ / 128, B_ * H_);    // 16 x 64
    attn_kernel<<<attn_grid, 128, 25088 * sizeof(float)>>>();

    dim3 out_grid(D_ / 64, 8192 / 128);   // 16 x 64
    out_gemm<<<out_grid, 128>>>(Wo, out);
}

// round 4
// speedup vs baseline: 1.5341x; 1.2325x over previous
#include <cuda_runtime.h>
#include <cuda_bf16.h>
#include <cstdint>

#define B_  4
#define S_  2048
#define D_  1024
#define H_  16
#define M_TOT 8192

// ---------------- device scratch (no allocs allowed) ----------------
__device__ float g_Q[B_ * H_ * S_ * 64];   // fp32 for attention
__device__ float g_K[B_ * H_ * S_ * 64];
__device__ float g_V[B_ * H_ * S_ * 64];

__device__ __align__(256) __nv_bfloat16 g_qh[M_TOT * D_], g_ql[M_TOT * D_];
__device__ __align__(256) __nv_bfloat16 g_kh[M_TOT * D_], g_kl[M_TOT * D_];
__device__ __align__(256) __nv_bfloat16 g_vh[M_TOT * D_], g_vl[M_TOT * D_];
__device__ __align__(256) __nv_bfloat16 g_wqh[H_ * 64 * D_], g_wql[H_ * 64 * D_];
__device__ __align__(256) __nv_bfloat16 g_wkh[H_ * 64 * D_], g_wkl[H_ * 64 * D_];
__device__ __align__(256) __nv_bfloat16 g_wvh[H_ * 64 * D_], g_wvl[H_ * 64 * D_];
__device__ __align__(256) __nv_bfloat16 g_woh[D_ * D_],     g_wol[D_ * D_];
__device__ __align__(256) __nv_bfloat16 g_Hh[M_TOT * D_],   g_Hl[M_TOT * D_];

// ---------------- PTX helpers (baseline ISA only: sm_80+) ----------------
__device__ __forceinline__ uint32_t smem_u32(const void* p) {
    uint32_t a;
    asm("{ .reg .u64 t; cvta.to.shared.u64 t, %1; cvt.u32.u64 %0, t; }"
        : "=r"(a) : "l"(p));
    return a;
}
__device__ __forceinline__ void cp16(uint32_t dst, const void* src) {
    asm volatile("cp.async.cg.shared.global [%0], [%1], 16;"
                 :: "r"(dst), "l"(src) : "memory");
}
#define CP_COMMIT() asm volatile("cp.async.commit_group;" ::: "memory")
#define CP_WAIT1()  asm volatile("cp.async.wait_group 1;"  ::: "memory")
#define CP_WAIT0()  asm volatile("cp.async.wait_group 0;"  ::: "memory")

__device__ __forceinline__ void ldsm_x4(uint32_t* r, uint32_t addr) {
    asm volatile("ldmatrix.sync.aligned.m8n8.x4.shared.b16 {%0,%1,%2,%3}, [%4];"
                 : "=r"(r[0]), "=r"(r[1]), "=r"(r[2]), "=r"(r[3]) : "r"(addr));
}
__device__ __forceinline__ void hmma(float* d, const uint32_t* a,
                                     uint32_t b0, uint32_t b1) {
    asm volatile("mma.sync.aligned.m16n8k16.row.col.f32.bf16.bf16.f32 "
                 "{%0,%1,%2,%3}, {%4,%5,%6,%7}, {%8,%9}, {%0,%1,%2,%3};"
                 : "+f"(d[0]), "+f"(d[1]), "+f"(d[2]), "+f"(d[3])
                 : "r"(a[0]), "r"(a[1]), "r"(a[2]), "r"(a[3]), "r"(b0), "r"(b1));
}
__device__ __forceinline__ uint32_t swz(uint32_t off) {
    return off ^ ((off >> 3) & 0x70);
}

// ---------------- conversion kernels ----------------
__device__ __forceinline__ void split_bf16(float x, __nv_bfloat16& h, __nv_bfloat16& l) {
    h = __float2bfloat16(x);
    l = __float2bfloat16(x - __bfloat162float(h));
}

__global__ __launch_bounds__(256) void conv_in(const float* __restrict__ x,
                                               __nv_bfloat16* __restrict__ hi,
                                               __nv_bfloat16* __restrict__ lo)
{
    size_t i = ((size_t)blockIdx.x * 256 + threadIdx.x) * 4;
    float4 v = *reinterpret_cast<const float4*>(x + i);
    __nv_bfloat16 h0, h1, h2, h3, l0, l1, l2, l3;
    split_bf16(v.x, h0, l0); split_bf16(v.y, h1, l1);
    split_bf16(v.z, h2, l2); split_bf16(v.w, h3, l3);
    *reinterpret_cast<__nv_bfloat162*>(hi + i)     = __halves2bfloat162(h0, h1);
    *reinterpret_cast<__nv_bfloat162*>(hi + i + 2) = __halves2bfloat162(h2, h3);
    *reinterpret_cast<__nv_bfloat162*>(lo + i)     = __halves2bfloat162(l0, l1);
    *reinterpret_cast<__nv_bfloat162*>(lo + i + 2) = __halves2bfloat162(l2, l3);
}

// W[h][k][n] (16,1024,64) -> Wt[h][n][k] hi/lo
__global__ __launch_bounds__(256) void conv_w(const float* __restrict__ W,
                                              __nv_bfloat16* __restrict__ hi,
                                              __nv_bfloat16* __restrict__ lo)
{
    int idx = blockIdx.x * 256 + threadIdx.x;        // h*65536 + n*1024 + k
    int k = idx & 1023;
    int n = (idx >> 10) & 63;
    int h = idx >> 16;
    float x = W[((size_t)h * D_ + k) * 64 + n];
    __nv_bfloat16 hh, ll;
    split_bf16(x, hh, ll);
    hi[idx] = hh; lo[idx] = ll;
}

// Wo[k][n] (1024,1024) -> Wot[n][k] hi/lo
__global__ __launch_bounds__(256) void conv_wo(const float* __restrict__ Wo,
                                               __nv_bfloat16* __restrict__ hi,
                                               __nv_bfloat16* __restrict__ lo)
{
    int idx = blockIdx.x * 256 + threadIdx.x;        // n*1024 + k
    int k = idx & 1023;
    int n = idx >> 10;
    float x = Wo[(size_t)k * D_ + n];
    __nv_bfloat16 hh, ll;
    split_bf16(x, hh, ll);
    hi[idx] = hh; lo[idx] = ll;
}

// ---------------- split-bf16 HMMA GEMM ----------------
// D[m,n] = sum_k A[m,k]*B[n,k]; A [8192,1024] hi/lo, B rows nb*64..+63 hi/lo.
// CTA tile 128x64, 4 warps (warp = 32 rows x 64 cols), K-chunks of 64,
// double-buffered cp.async. 3-MMA split: Ah*Bh + Ah*Bl + Al*Bh, fp32 accum.
#define STAGE_BYTES 49152
#define A_HI_OFF 0
#define A_LO_OFF 16384
#define B_HI_OFF 32768
#define B_LO_OFF 40960
#define MMA_SMEM (2 * STAGE_BYTES)

__global__ __launch_bounds__(128) void mma_gemm(const __nv_bfloat16* __restrict__ ah,
                                                const __nv_bfloat16* __restrict__ al,
                                                const __nv_bfloat16* __restrict__ bh,
                                                const __nv_bfloat16* __restrict__ bl,
                                                float* __restrict__ outp, int mode)
{
    extern __shared__ char sm[];
    const uint32_t smem = smem_u32(sm);
    const int tid  = threadIdx.x;
    const int wid  = tid >> 5;
    const int lane = tid & 31;
    const int nb   = blockIdx.x;
    const int m0   = blockIdx.y * 128;

    const __nv_bfloat16* aH = ah + (size_t)m0 * D_;
    const __nv_bfloat16* aL = al + (size_t)m0 * D_;
    const __nv_bfloat16* bH = bh + (size_t)nb * 64 * D_;
    const __nv_bfloat16* bL = bl + (size_t)nb * 64 * D_;

    // ---- stage loader (all 128 threads) ----
    const int brow = tid >> 1;          // B row 0..63
    const int bhalf = tid & 1;          // which 64B half of the row
    auto load_stage = [&](int c, int buf) {
        const uint32_t sb = smem + buf * STAGE_BYTES;
        const int k0 = c * 64;
        // A: thread = row, 8 x 16B for hi and lo
        const char* gh = (const char*)(aH + (size_t)tid * D_ + k0);
        const char* gl = (const char*)(aL + (size_t)tid * D_ + k0);
        #pragma unroll
        for (int i = 0; i < 8; ++i) {
            uint32_t sw = swz(tid * 128 + i * 16);
            cp16(sb + A_HI_OFF + sw, gh + i * 16);
            cp16(sb + A_LO_OFF + sw, gl + i * 16);
        }
        // B: 2 threads per row, 4 x 16B each for hi and lo
        const char* gbh = (const char*)(bH + (size_t)brow * D_ + k0 + bhalf * 32);
        const char* gbl = (const char*)(bL + (size_t)brow * D_ + k0 + bhalf * 32);
        #pragma unroll
        for (int j = 0; j < 4; ++j) {
            uint32_t sw = swz(brow * 128 + bhalf * 64 + j * 16);
            cp16(sb + B_HI_OFF + sw, gbh + j * 16);
            cp16(sb + B_LO_OFF + sw, gbl + j * 16);
        }
    };

    float acc[2][8][4] = {};
    const int mbase = wid * 32;

    load_stage(0, 0);
    CP_COMMIT();

    for (int c = 0; c < 16; ++c) {
        const int buf = c & 1;
        if (c < 15) { load_stage(c + 1, buf ^ 1); CP_COMMIT(); }
        if (c < 15) CP_WAIT1(); else CP_WAIT0();
        __syncthreads();

        const uint32_t sb = smem + buf * STAGE_BYTES;
        #pragma unroll
        for (int ks = 0; ks < 4; ++ks) {
            const int kb = ks * 32;   // byte offset of k within 128B row

            // A fragments (2 m-frags, hi+lo)
            uint32_t ahi[2][4], alo[2][4];
            #pragma unroll
            for (int mf = 0; mf < 2; ++mf) {
                uint32_t off = (uint32_t)(mbase + mf * 16 + (lane & 15)) * 128
                             + kb + (lane >> 4) * 16;
                uint32_t sw = swz(off);
                ldsm_x4(ahi[mf], sb + A_HI_OFF + sw);
                ldsm_x4(alo[mf], sb + A_LO_OFF + sw);
            }
            // B fragments (4 n-pairs of 16, hi+lo)
            uint32_t bhi[4][4], blo[4][4];
            #pragma unroll
            for (int np = 0; np < 4; ++np) {
                uint32_t n  = np * 16 + (lane & 7) + ((lane >> 4) << 3);
                uint32_t off = n * 128 + kb + ((lane >> 3) & 1) * 16;
                uint32_t sw = swz(off);
                ldsm_x4(bhi[np], sb + B_HI_OFF + sw);
                ldsm_x4(blo[np], sb + B_LO_OFF + sw);
            }
            // MMAs: 2m x 8n x (hh + hl + lh)
            #pragma unroll
            for (int mf = 0; mf < 2; ++mf) {
                #pragma unroll
                for (int nf = 0; nf < 8; ++nf) {
                    const int np = nf >> 1, sel = (nf & 1) * 2;
                    hmma(acc[mf][nf], ahi[mf], bhi[np][sel], bhi[np][sel + 1]);
                    hmma(acc[mf][nf], ahi[mf], blo[np][sel], blo[np][sel + 1]);
                    hmma(acc[mf][nf], alo[mf], bhi[np][sel], bhi[np][sel + 1]);
                }
            }
        }
        __syncthreads();
    }

    // ---- epilogue ----
    const int g = lane >> 2;
    const int t = lane & 3;
    #pragma unroll
    for (int mf = 0; mf < 2; ++mf) {
        #pragma unroll
        for (int half = 0; half < 2; ++half) {
            const int m = m0 + mbase + mf * 16 + g + half * 8;
            float* orow;
            if (mode < 3) {
                int b = m >> 11, s = m & (S_ - 1);
                float* base = (mode == 0) ? g_Q : ((mode == 1) ? g_K : g_V);
                orow = base + ((size_t)(b * H_ + nb) * S_ + s) * 64;
            } else {
                orow = outp + (size_t)m * D_ + nb * 64;
            }
            #pragma unroll
            for (int nf = 0; nf < 8; ++nf) {
                float2 v = make_float2(acc[mf][nf][half * 2], acc[mf][nf][half * 2 + 1]);
                *reinterpret_cast<float2*>(orow + nf * 8 + t * 2) = v;
            }
        }
    }
}

// ---------------- flash attention (fp32), epilogue -> bf16 hi/lo ----------------
#define PS_PAD 68

__global__ __launch_bounds__(128) void attn_kernel()
{
    extern __shared__ float smf[];
    float* Qs = smf;            // [d][q]
    float* Ks = smf + 8192;     // [d][k]
    float* Vs = smf + 12288;    // [k][dv]
    float* Ps = smf + 16384;    // [q][kk]

    const int tid = threadIdx.x;
    const int tx  = tid & 7;
    const int ty  = tid >> 3;
    const int bh  = blockIdx.y;
    const int q0  = blockIdx.x * 128;

    {
        const float* Qg = &g_Q[((size_t)bh * S_ + q0) * 64];
        #pragma unroll
        for (int i = 0; i < 16; ++i) {
            int idx = i * 128 + tid;
            int r   = idx >> 4;
            int col = (idx & 15) * 4;
            float4 qv = *reinterpret_cast<const float4*>(&Qg[r * 64 + col]);
            Qs[(col + 0) * 128 + r] = qv.x * 0.125f;
            Qs[(col + 1) * 128 + r] = qv.y * 0.125f;
            Qs[(col + 2) * 128 + r] = qv.z * 0.125f;
            Qs[(col + 3) * 128 + r] = qv.w * 0.125f;
        }
    }

    float O[8][8] = {};
    float mrow[8], lrow[8];
    #pragma unroll
    for (int i = 0; i < 8; ++i) { mrow[i] = -1e30f; lrow[i] = 0.0f; }

    const float* Kbase = &g_K[(size_t)bh * S_ * 64];
    const float* Vbase = &g_V[(size_t)bh * S_ * 64];

    for (int kt = 0; kt < S_; kt += 64) {
        #pragma unroll
        for (int i = 0; i < 8; ++i) {
            int idx = i * 128 + tid;
            int r   = idx >> 4;
            int col = (idx & 15) * 4;
            float4 kv = *reinterpret_cast<const float4*>(&Kbase[(size_t)(kt + r) * 64 + col]);
            Ks[(col + 0) * 64 + r] = kv.x;
            Ks[(col + 1) * 64 + r] = kv.y;
            Ks[(col + 2) * 64 + r] = kv.z;
            Ks[(col + 3) * 64 + r] = kv.w;
            *reinterpret_cast<float4*>(&Vs[r * 64 + col]) =
                *reinterpret_cast<const float4*>(&Vbase[(size_t)(kt + r) * 64 + col]);
        }
        __syncthreads();

        float s[8][8] = {};
        #pragma unroll
        for (int d = 0; d < 64; ++d) {
            float a[8], b[8];
            *reinterpret_cast<float4*>(&a[0]) = *reinterpret_cast<const float4*>(&Qs[d * 128 + ty * 8]);
            *reinterpret_cast<float4*>(&a[4]) = *reinterpret_cast<const float4*>(&Qs[d * 128 + ty * 8 + 4]);
            *reinterpret_cast<float4*>(&b[0]) = *reinterpret_cast<const float4*>(&Ks[d * 64 + tx * 8]);
            *reinterpret_cast<float4*>(&b[4]) = *reinterpret_cast<const float4*>(&Ks[d * 64 + tx * 8 + 4]);
            #pragma unroll
            for (int i = 0; i < 8; ++i)
                #pragma unroll
                for (int j = 0; j < 8; ++j)
                    s[i][j] = fmaf(a[i], b[j], s[i][j]);
        }

        #pragma unroll
        for (int i = 0; i < 8; ++i) {
            float tm = s[i][0];
            #pragma unroll
            for (int j = 1; j < 8; ++j) tm = fmaxf(tm, s[i][j]);
            tm = fmaxf(tm, __shfl_xor_sync(0xffffffffu, tm, 1));
            tm = fmaxf(tm, __shfl_xor_sync(0xffffffffu, tm, 2));
            tm = fmaxf(tm, __shfl_xor_sync(0xffffffffu, tm, 4));

            float mnew = fmaxf(mrow[i], tm);
            float corr = __expf(mrow[i] - mnew);
            mrow[i] = mnew;

            float rsum = 0.0f;
            float p[8];
            #pragma unroll
            for (int j = 0; j < 8; ++j) {
                p[j] = __expf(s[i][j] - mnew);
                rsum += p[j];
            }
            rsum += __shfl_xor_sync(0xffffffffu, rsum, 1);
            rsum += __shfl_xor_sync(0xffffffffu, rsum, 2);
            rsum += __shfl_xor_sync(0xffffffffu, rsum, 4);
            lrow[i] = lrow[i] * corr + rsum;

            #pragma unroll
            for (int cc = 0; cc < 8; ++cc) O[i][cc] *= corr;

            float* pr = &Ps[(ty * 8 + i) * PS_PAD + tx * 8];
            *reinterpret_cast<float4*>(&pr[0]) = make_float4(p[0], p[1], p[2], p[3]);
            *reinterpret_cast<float4*>(&pr[4]) = make_float4(p[4], p[5], p[6], p[7]);
        }
        __syncthreads();

        #pragma unroll 8
        for (int kk = 0; kk < 64; ++kk) {
            float b[8];
            *reinterpret_cast<float4*>(&b[0]) = *reinterpret_cast<const float4*>(&Vs[kk * 64 + tx * 8]);
            *reinterpret_cast<float4*>(&b[4]) = *reinterpret_cast<const float4*>(&Vs[kk * 64 + tx * 8 + 4]);
            #pragma unroll
            for (int i = 0; i < 8; ++i) {
                float pa = Ps[(ty * 8 + i) * PS_PAD + kk];
                #pragma unroll
                for (int cc = 0; cc < 8; ++cc)
                    O[i][cc] = fmaf(pa, b[cc], O[i][cc]);
            }
        }
        __syncthreads();
    }

    // epilogue: normalize, split to bf16 hi/lo, concat-head layout
    const int b = bh >> 4;
    const int h = bh & 15;
    #pragma unroll
    for (int i = 0; i < 8; ++i) {
        float inv = 1.0f / lrow[i];
        int srow  = q0 + ty * 8 + i;
        size_t base = ((size_t)(b * S_ + srow)) * D_ + h * 64 + tx * 8;
        union { __nv_bfloat16 v[8]; uint4 u; } hb, lb;
        #pragma unroll
        for (int cc = 0; cc < 8; ++cc) {
            float o = O[i][cc] * inv;
            split_bf16(o, hb.v[cc], lb.v[cc]);
        }
        *reinterpret_cast<uint4*>(g_Hh + base) = hb.u;
        *reinterpret_cast<uint4*>(g_Hl + base) = lb.u;
    }
}

// ---------------- launch ----------------
extern "C" void kernel_launch(void* const* d_in, const int* in_sizes, int n_in,
                              void* d_out, int out_size)
{
    const float* q  = (const float*)d_in[0];
    const float* k  = (const float*)d_in[1];
    const float* v  = (const float*)d_in[2];
    const float* Wq = (const float*)d_in[3];
    const float* Wk = (const float*)d_in[4];
    const float* Wv = (const float*)d_in[5];
    const float* Wo = (const float*)d_in[6];
    float* out = (float*)d_out;

    static bool configured = false;
    if (!configured) {
        cudaFuncSetAttribute(attn_kernel, cudaFuncAttributeMaxDynamicSharedMemorySize,
                             25088 * (int)sizeof(float));
        cudaFuncSetAttribute(mma_gemm, cudaFuncAttributeMaxDynamicSharedMemorySize,
                             MMA_SMEM);
        configured = true;
    }

    __nv_bfloat16 *qh, *ql, *kh, *kl, *vh, *vl;
    __nv_bfloat16 *wqh, *wql, *wkh, *wkl, *wvh, *wvl, *woh, *wol, *Hh, *Hl;
    cudaGetSymbolAddress((void**)&qh, g_qh);   cudaGetSymbolAddress((void**)&ql, g_ql);
    cudaGetSymbolAddress((void**)&kh, g_kh);   cudaGetSymbolAddress((void**)&kl, g_kl);
    cudaGetSymbolAddress((void**)&vh, g_vh);   cudaGetSymbolAddress((void**)&vl, g_vl);
    cudaGetSymbolAddress((void**)&wqh, g_wqh); cudaGetSymbolAddress((void**)&wql, g_wql);
    cudaGetSymbolAddress((void**)&wkh, g_wkh); cudaGetSymbolAddress((void**)&wkl, g_wkl);
    cudaGetSymbolAddress((void**)&wvh, g_wvh); cudaGetSymbolAddress((void**)&wvl, g_wvl);
    cudaGetSymbolAddress((void**)&woh, g_woh); cudaGetSymbolAddress((void**)&wol, g_wol);
    cudaGetSymbolAddress((void**)&Hh, g_Hh);   cudaGetSymbolAddress((void**)&Hl, g_Hl);

    conv_in<<<8192, 256>>>(q, qh, ql);
    conv_in<<<8192, 256>>>(k, kh, kl);
    conv_in<<<8192, 256>>>(v, vh, vl);
    conv_w<<<4096, 256>>>(Wq, wqh, wql);
    conv_w<<<4096, 256>>>(Wk, wkh, wkl);
    conv_w<<<4096, 256>>>(Wv, wvh, wvl);
    conv_wo<<<4096, 256>>>(Wo, woh, wol);

    dim3 gemm_grid(H_, M_TOT / 128);     // 16 x 64
    mma_gemm<<<gemm_grid, 128, MMA_SMEM>>>(qh, ql, wqh, wql, nullptr, 0);
    mma_gemm<<<gemm_grid, 128, MMA_SMEM>>>(kh, kl, wkh, wkl, nullptr, 1);
    mma_gemm<<<gemm_grid, 128, MMA_SMEM>>>(vh, vl, wvh, wvl, nullptr, 2);

    dim3 attn_grid(S_ / 128, B_ * H_);   // 16 x 64
    attn_kernel<<<attn_grid, 128, 25088 * sizeof(float)>>>();

    dim3 out_grid(D_ / 64, M_TOT / 128); // 16 x 64
    mma_gemm<<<out_grid, 128, MMA_SMEM>>>(Hh, Hl, woh, wol, out, 3);
}

// round 5
// speedup vs baseline: 2.8884x; 1.8828x over previous
#include <cuda_runtime.h>
#include <cuda_bf16.h>
#include <cstdint>

#define B_  4
#define S_  2048
#define D_  1024
#define H_  16
#define M_TOT 8192

// ---------------- device scratch (no allocs allowed) ----------------
// inputs/weights split to bf16 hi/lo
__device__ __align__(256) __nv_bfloat16 g_qh[M_TOT * D_], g_ql[M_TOT * D_];
__device__ __align__(256) __nv_bfloat16 g_kh[M_TOT * D_], g_kl[M_TOT * D_];
__device__ __align__(256) __nv_bfloat16 g_vh[M_TOT * D_], g_vl[M_TOT * D_];
__device__ __align__(256) __nv_bfloat16 g_wqh[H_ * 64 * D_], g_wql[H_ * 64 * D_];
__device__ __align__(256) __nv_bfloat16 g_wkh[H_ * 64 * D_], g_wkl[H_ * 64 * D_];
__device__ __align__(256) __nv_bfloat16 g_wvh[H_ * 64 * D_], g_wvl[H_ * 64 * D_];
__device__ __align__(256) __nv_bfloat16 g_woh[D_ * D_],     g_wol[D_ * D_];
// projected tensors, bf16 hi/lo, MMA-ready layouts
__device__ __align__(256) __nv_bfloat16 g_Qh[64 * S_ * 64],  g_Ql[64 * S_ * 64];   // [bh][s][dk] (pre-scaled)
__device__ __align__(256) __nv_bfloat16 g_Kh[64 * S_ * 64],  g_Kl[64 * S_ * 64];   // [bh][key][dk]
__device__ __align__(256) __nv_bfloat16 g_Vth[64 * 64 * S_], g_Vtl[64 * 64 * S_];  // [bh][dv][key]
// attention output (concat heads), bf16 hi/lo
__device__ __align__(256) __nv_bfloat16 g_Hh[M_TOT * D_], g_Hl[M_TOT * D_];

// ---------------- PTX helpers (baseline ISA: sm_80+) ----------------
__device__ __forceinline__ uint32_t smem_u32(const void* p) {
    uint32_t a;
    asm("{ .reg .u64 t; cvta.to.shared.u64 t, %1; cvt.u32.u64 %0, t; }"
        : "=r"(a) : "l"(p));
    return a;
}
__device__ __forceinline__ void cp16(uint32_t dst, const void* src) {
    asm volatile("cp.async.cg.shared.global [%0], [%1], 16;"
                 :: "r"(dst), "l"(src) : "memory");
}
#define CP_COMMIT() asm volatile("cp.async.commit_group;" ::: "memory")
#define CP_WAIT1()  asm volatile("cp.async.wait_group 1;"  ::: "memory")
#define CP_WAIT0()  asm volatile("cp.async.wait_group 0;"  ::: "memory")

__device__ __forceinline__ void ldsm_x4(uint32_t* r, uint32_t addr) {
    asm volatile("ldmatrix.sync.aligned.m8n8.x4.shared.b16 {%0,%1,%2,%3}, [%4];"
                 : "=r"(r[0]), "=r"(r[1]), "=r"(r[2]), "=r"(r[3]) : "r"(addr));
}
__device__ __forceinline__ void hmma(float* d, const uint32_t* a,
                                     uint32_t b0, uint32_t b1) {
    asm volatile("mma.sync.aligned.m16n8k16.row.col.f32.bf16.bf16.f32 "
                 "{%0,%1,%2,%3}, {%4,%5,%6,%7}, {%8,%9}, {%0,%1,%2,%3};"
                 : "+f"(d[0]), "+f"(d[1]), "+f"(d[2]), "+f"(d[3])
                 : "r"(a[0]), "r"(a[1]), "r"(a[2]), "r"(a[3]), "r"(b0), "r"(b1));
}
__device__ __forceinline__ uint32_t swz(uint32_t off) {
    return off ^ ((off >> 3) & 0x70);
}
__device__ __forceinline__ void split_bf16(float x, __nv_bfloat16& h, __nv_bfloat16& l) {
    h = __float2bfloat16(x);
    l = __float2bfloat16(x - __bfloat162float(h));
}
// pack two fp32 into bf16x2 hi reg, and their residuals into lo reg
__device__ __forceinline__ uint32_t packsplit(float x, float y, uint32_t& lo) {
    __nv_bfloat16 hx, hy, lx, ly;
    split_bf16(x, hx, lx);
    split_bf16(y, hy, ly);
    __nv_bfloat162 hv = __halves2bfloat162(hx, hy);
    __nv_bfloat162 lv = __halves2bfloat162(lx, ly);
    lo = *reinterpret_cast<uint32_t*>(&lv);
    return *reinterpret_cast<uint32_t*>(&hv);
}

// ---------------- conversion kernels ----------------
__global__ __launch_bounds__(256) void conv_in(const float* __restrict__ x,
                                               __nv_bfloat16* __restrict__ hi,
                                               __nv_bfloat16* __restrict__ lo)
{
    size_t i = ((size_t)blockIdx.x * 256 + threadIdx.x) * 4;
    float4 v = *reinterpret_cast<const float4*>(x + i);
    __nv_bfloat16 h0, h1, h2, h3, l0, l1, l2, l3;
    split_bf16(v.x, h0, l0); split_bf16(v.y, h1, l1);
    split_bf16(v.z, h2, l2); split_bf16(v.w, h3, l3);
    *reinterpret_cast<__nv_bfloat162*>(hi + i)     = __halves2bfloat162(h0, h1);
    *reinterpret_cast<__nv_bfloat162*>(hi + i + 2) = __halves2bfloat162(h2, h3);
    *reinterpret_cast<__nv_bfloat162*>(lo + i)     = __halves2bfloat162(l0, l1);
    *reinterpret_cast<__nv_bfloat162*>(lo + i + 2) = __halves2bfloat162(l2, l3);
}

// W[h][k][n] (16,1024,64) -> Wt[h][n][k] hi/lo
__global__ __launch_bounds__(256) void conv_w(const float* __restrict__ W,
                                              __nv_bfloat16* __restrict__ hi,
                                              __nv_bfloat16* __restrict__ lo)
{
    int idx = blockIdx.x * 256 + threadIdx.x;        // h*65536 + n*1024 + k
    int k = idx & 1023;
    int n = (idx >> 10) & 63;
    int h = idx >> 16;
    float x = W[((size_t)h * D_ + k) * 64 + n];
    __nv_bfloat16 hh, ll;
    split_bf16(x, hh, ll);
    hi[idx] = hh; lo[idx] = ll;
}

// Wo[k][n] (1024,1024) -> Wot[n][k] hi/lo
__global__ __launch_bounds__(256) void conv_wo(const float* __restrict__ Wo,
                                               __nv_bfloat16* __restrict__ hi,
                                               __nv_bfloat16* __restrict__ lo)
{
    int idx = blockIdx.x * 256 + threadIdx.x;        // n*1024 + k
    int k = idx & 1023;
    int n = idx >> 10;
    float x = Wo[(size_t)k * D_ + n];
    __nv_bfloat16 hh, ll;
    split_bf16(x, hh, ll);
    hi[idx] = hh; lo[idx] = ll;
}

// ---------------- split-bf16 HMMA GEMM ----------------
// D[m,n] = sum_k A[m,k]*B[n,k]; CTA 128x64, 4 warps, K-chunks 64, double-buffered.
// mode 0: Q  -> g_Qh/g_Ql [bh][s][64], scaled 0.125
// mode 1: K  -> g_Kh/g_Kl [bh][key][64]
// mode 2: V  -> g_Vth/g_Vtl [bh][dv][key] (transposed scatter)
// mode 3: fp32 -> outp[m][1024]
#define STAGE_BYTES 49152
#define A_HI_OFF 0
#define A_LO_OFF 16384
#define B_HI_OFF 32768
#define B_LO_OFF 40960
#define MMA_SMEM (2 * STAGE_BYTES)

__global__ __launch_bounds__(128) void mma_gemm(const __nv_bfloat16* __restrict__ ah,
                                                const __nv_bfloat16* __restrict__ al,
                                                const __nv_bfloat16* __restrict__ bh,
                                                const __nv_bfloat16* __restrict__ bl,
                                                float* __restrict__ outp, int mode)
{
    extern __shared__ char sm[];
    const uint32_t smem = smem_u32(sm);
    const int tid  = threadIdx.x;
    const int wid  = tid >> 5;
    const int lane = tid & 31;
    const int nb   = blockIdx.x;
    const int m0   = blockIdx.y * 128;

    const __nv_bfloat16* aH = ah + (size_t)m0 * D_;
    const __nv_bfloat16* aL = al + (size_t)m0 * D_;
    const __nv_bfloat16* bH = bh + (size_t)nb * 64 * D_;
    const __nv_bfloat16* bL = bl + (size_t)nb * 64 * D_;

    const int brow = tid >> 1;
    const int bhalf = tid & 1;
    auto load_stage = [&](int c, int buf) {
        const uint32_t sb = smem + buf * STAGE_BYTES;
        const int k0 = c * 64;
        const char* gh = (const char*)(aH + (size_t)tid * D_ + k0);
        const char* gl = (const char*)(aL + (size_t)tid * D_ + k0);
        #pragma unroll
        for (int i = 0; i < 8; ++i) {
            uint32_t sw = swz(tid * 128 + i * 16);
            cp16(sb + A_HI_OFF + sw, gh + i * 16);
            cp16(sb + A_LO_OFF + sw, gl + i * 16);
        }
        const char* gbh = (const char*)(bH + (size_t)brow * D_ + k0 + bhalf * 32);
        const char* gbl = (const char*)(bL + (size_t)brow * D_ + k0 + bhalf * 32);
        #pragma unroll
        for (int j = 0; j < 4; ++j) {
            uint32_t sw = swz(brow * 128 + bhalf * 64 + j * 16);
            cp16(sb + B_HI_OFF + sw, gbh + j * 16);
            cp16(sb + B_LO_OFF + sw, gbl + j * 16);
        }
    };

    float acc[2][8][4] = {};
    const int mbase = wid * 32;

    load_stage(0, 0);
    CP_COMMIT();

    for (int c = 0; c < 16; ++c) {
        const int buf = c & 1;
        if (c < 15) { load_stage(c + 1, buf ^ 1); CP_COMMIT(); }
        if (c < 15) CP_WAIT1(); else CP_WAIT0();
        __syncthreads();

        const uint32_t sb = smem + buf * STAGE_BYTES;
        #pragma unroll
        for (int ks = 0; ks < 4; ++ks) {
            const int kb = ks * 32;
            uint32_t ahi[2][4], alo[2][4];
            #pragma unroll
            for (int mf = 0; mf < 2; ++mf) {
                uint32_t off = (uint32_t)(mbase + mf * 16 + (lane & 15)) * 128
                             + kb + (lane >> 4) * 16;
                uint32_t sw = swz(off);
                ldsm_x4(ahi[mf], sb + A_HI_OFF + sw);
                ldsm_x4(alo[mf], sb + A_LO_OFF + sw);
            }
            uint32_t bhi[4][4], blo[4][4];
            #pragma unroll
            for (int np = 0; np < 4; ++np) {
                uint32_t n  = np * 16 + (lane & 7) + ((lane >> 4) << 3);
                uint32_t off = n * 128 + kb + ((lane >> 3) & 1) * 16;
                uint32_t sw = swz(off);
                ldsm_x4(bhi[np], sb + B_HI_OFF + sw);
                ldsm_x4(blo[np], sb + B_LO_OFF + sw);
            }
            #pragma unroll
            for (int mf = 0; mf < 2; ++mf) {
                #pragma unroll
                for (int nf = 0; nf < 8; ++nf) {
                    const int np = nf >> 1, sel = (nf & 1) * 2;
                    hmma(acc[mf][nf], ahi[mf], bhi[np][sel], bhi[np][sel + 1]);
                    hmma(acc[mf][nf], ahi[mf], blo[np][sel], blo[np][sel + 1]);
                    hmma(acc[mf][nf], alo[mf], bhi[np][sel], bhi[np][sel + 1]);
                }
            }
        }
        __syncthreads();
    }

    // ---- epilogue ----
    const int g = lane >> 2;
    const int t = lane & 3;
    #pragma unroll
    for (int mf = 0; mf < 2; ++mf) {
        #pragma unroll
        for (int half = 0; half < 2; ++half) {
            const int m = m0 + mbase + mf * 16 + half * 8 + g;
            if (mode == 3) {
                float* orow = outp + (size_t)m * D_ + nb * 64;
                #pragma unroll
                for (int nf = 0; nf < 8; ++nf)
                    *reinterpret_cast<float2*>(orow + nf * 8 + t * 2) =
                        make_float2(acc[mf][nf][half * 2], acc[mf][nf][half * 2 + 1]);
            } else {
                const int b = m >> 11, s = m & (S_ - 1);
                const int bh_ = b * H_ + nb;
                if (mode < 2) {
                    const float sc = (mode == 0) ? 0.125f : 1.0f;
                    __nv_bfloat16* dh = (mode == 0) ? g_Qh : g_Kh;
                    __nv_bfloat16* dl = (mode == 0) ? g_Ql : g_Kl;
                    size_t base = ((size_t)bh_ * S_ + s) * 64;
                    #pragma unroll
                    for (int nf = 0; nf < 8; ++nf) {
                        uint32_t lo, hi = packsplit(acc[mf][nf][half * 2] * sc,
                                                    acc[mf][nf][half * 2 + 1] * sc, lo);
                        *reinterpret_cast<uint32_t*>(dh + base + nf * 8 + t * 2) = hi;
                        *reinterpret_cast<uint32_t*>(dl + base + nf * 8 + t * 2) = lo;
                    }
                } else {
                    // V transpose: element (s=key, dv) -> [bh][dv][key]
                    #pragma unroll
                    for (int nf = 0; nf < 8; ++nf) {
                        #pragma unroll
                        for (int e = 0; e < 2; ++e) {
                            int dv = nf * 8 + t * 2 + e;
                            __nv_bfloat16 hh, ll;
                            split_bf16(acc[mf][nf][half * 2 + e], hh, ll);
                            size_t addr = ((size_t)bh_ * 64 + dv) * S_ + s;
                            g_Vth[addr] = hh;
                            g_Vtl[addr] = ll;
                        }
                    }
                }
            }
        }
    }
}

// ---------------- tensor-core flash attention (split-bf16 HMMA) ----------------
// CTA = 128 q rows of one (bh). 4 warps x 32 rows. K-tiles of 64 keys,
// double-buffered cp.async. Scores and P stay in registers.
#define KH_OFF 0
#define KL_OFF 8192
#define VH_OFF 16384
#define VL_OFF 24576
#define AT_STAGE 32768
#define QH_OFF 65536
#define QL_OFF (65536 + 16384)
#define ATT_SMEM 98304

__global__ __launch_bounds__(128) void attn_mma()
{
    extern __shared__ char sm[];
    const uint32_t smem = smem_u32(sm);
    const int tid  = threadIdx.x;
    const int wid  = tid >> 5;
    const int lane = tid & 31;
    const int bh   = blockIdx.y;
    const int q0   = blockIdx.x * 128;
    const int mbase = wid * 32;

    // Q tile async load (bundled into group 0)
    {
        const char* gh = (const char*)(g_Qh + ((size_t)bh * S_ + q0 + tid) * 64);
        const char* gl = (const char*)(g_Ql + ((size_t)bh * S_ + q0 + tid) * 64);
        #pragma unroll
        for (int i = 0; i < 8; ++i) {
            uint32_t sw = swz(tid * 128 + i * 16);
            cp16(smem + QH_OFF + sw, gh + i * 16);
            cp16(smem + QL_OFF + sw, gl + i * 16);
        }
    }
    const int r2 = tid >> 1, hf = tid & 1;
    auto load_stage = [&](int kt, int buf) {
        const uint32_t sb = smem + buf * AT_STAGE;
        const char* kh = (const char*)(g_Kh + ((size_t)bh * S_ + kt + r2) * 64) + hf * 64;
        const char* kl = (const char*)(g_Kl + ((size_t)bh * S_ + kt + r2) * 64) + hf * 64;
        const char* vh = (const char*)(g_Vth + ((size_t)bh * 64 + r2) * S_ + kt) + hf * 64;
        const char* vl = (const char*)(g_Vtl + ((size_t)bh * 64 + r2) * S_ + kt) + hf * 64;
        #pragma unroll
        for (int j = 0; j < 4; ++j) {
            uint32_t sw = swz(r2 * 128 + hf * 64 + j * 16);
            cp16(sb + KH_OFF + sw, kh + j * 16);
            cp16(sb + KL_OFF + sw, kl + j * 16);
            cp16(sb + VH_OFF + sw, vh + j * 16);
            cp16(sb + VL_OFF + sw, vl + j * 16);
        }
    };
    load_stage(0, 0);  CP_COMMIT();
    load_stage(64, 1); CP_COMMIT();
    CP_WAIT1();
    __syncthreads();

    // persistent Q hi fragments (Q lo re-loaded per use)
    uint32_t qh[2][4][4];
    #pragma unroll
    for (int mf = 0; mf < 2; ++mf)
        #pragma unroll
        for (int ks = 0; ks < 4; ++ks) {
            uint32_t off = (uint32_t)(mbase + mf * 16 + (lane & 15)) * 128
                         + ks * 32 + (lane >> 4) * 16;
            ldsm_x4(qh[mf][ks], smem + QH_OFF + swz(off));
        }

    float O[2][8][4] = {};
    float mrow[4] = {-1e30f, -1e30f, -1e30f, -1e30f};
    float lrow[4] = {};

    for (int c = 0; c < 32; ++c) {
        const uint32_t sb = smem + (c & 1) * AT_STAGE;

        // ---- QK^T (3-MMA split) ----
        float s[2][8][4] = {};
        #pragma unroll
        for (int ks = 0; ks < 4; ++ks) {
            uint32_t ql_[2][4];
            #pragma unroll
            for (int mf = 0; mf < 2; ++mf) {
                uint32_t off = (uint32_t)(mbase + mf * 16 + (lane & 15)) * 128
                             + ks * 32 + (lane >> 4) * 16;
                ldsm_x4(ql_[mf], smem + QL_OFF + swz(off));
            }
            #pragma unroll
            for (int np = 0; np < 4; ++np) {
                uint32_t n  = np * 16 + (lane & 7) + ((lane >> 4) << 3);
                uint32_t off = n * 128 + ks * 32 + ((lane >> 3) & 1) * 16;
                uint32_t sw = swz(off);
                uint32_t kbh[4], kbl[4];
                ldsm_x4(kbh, sb + KH_OFF + sw);
                ldsm_x4(kbl, sb + KL_OFF + sw);
                #pragma unroll
                for (int mf = 0; mf < 2; ++mf) {
                    #pragma unroll
                    for (int x = 0; x < 2; ++x) {
                        const int nf = np * 2 + x;
                        hmma(s[mf][nf], qh[mf][ks], kbh[x * 2], kbh[x * 2 + 1]);
                        hmma(s[mf][nf], qh[mf][ks], kbl[x * 2], kbl[x * 2 + 1]);
                        hmma(s[mf][nf], ql_[mf],    kbh[x * 2], kbh[x * 2 + 1]);
                    }
                }
            }
        }

        // ---- online softmax on fragments ----
        #pragma unroll
        for (int mf = 0; mf < 2; ++mf) {
            #pragma unroll
            for (int half = 0; half < 2; ++half) {
                const int idx = mf * 2 + half;
                float rmax = -1e30f;
                #pragma unroll
                for (int nf = 0; nf < 8; ++nf)
                    rmax = fmaxf(rmax, fmaxf(s[mf][nf][half * 2], s[mf][nf][half * 2 + 1]));
                rmax = fmaxf(rmax, __shfl_xor_sync(0xffffffffu, rmax, 1));
                rmax = fmaxf(rmax, __shfl_xor_sync(0xffffffffu, rmax, 2));
                const float mnew = fmaxf(mrow[idx], rmax);
                const float corr = __expf(mrow[idx] - mnew);
                float rsum = 0.0f;
                #pragma unroll
                for (int nf = 0; nf < 8; ++nf) {
                    float p0 = __expf(s[mf][nf][half * 2]     - mnew);
                    float p1 = __expf(s[mf][nf][half * 2 + 1] - mnew);
                    s[mf][nf][half * 2]     = p0;
                    s[mf][nf][half * 2 + 1] = p1;
                    rsum += p0 + p1;
                }
                rsum += __shfl_xor_sync(0xffffffffu, rsum, 1);
                rsum += __shfl_xor_sync(0xffffffffu, rsum, 2);
                lrow[idx] = lrow[idx] * corr + rsum;
                mrow[idx] = mnew;
                #pragma unroll
                for (int nf = 0; nf < 8; ++nf) {
                    O[mf][nf][half * 2]     *= corr;
                    O[mf][nf][half * 2 + 1] *= corr;
                }
            }
        }

        // ---- P @ V (3-MMA split; P frags repacked from accum regs) ----
        #pragma unroll
        for (int kk = 0; kk < 4; ++kk) {
            uint32_t pah[2][4], pal[2][4];
            #pragma unroll
            for (int mf = 0; mf < 2; ++mf) {
                pah[mf][0] = packsplit(s[mf][2 * kk][0],     s[mf][2 * kk][1],     pal[mf][0]);
                pah[mf][1] = packsplit(s[mf][2 * kk][2],     s[mf][2 * kk][3],     pal[mf][1]);
                pah[mf][2] = packsplit(s[mf][2 * kk + 1][0], s[mf][2 * kk + 1][1], pal[mf][2]);
                pah[mf][3] = packsplit(s[mf][2 * kk + 1][2], s[mf][2 * kk + 1][3], pal[mf][3]);
            }
            #pragma unroll
            for (int np = 0; np < 4; ++np) {
                uint32_t n  = np * 16 + (lane & 7) + ((lane >> 4) << 3);
                uint32_t off = n * 128 + kk * 32 + ((lane >> 3) & 1) * 16;
                uint32_t sw = swz(off);
                uint32_t vbh[4], vbl[4];
                ldsm_x4(vbh, sb + VH_OFF + sw);
                ldsm_x4(vbl, sb + VL_OFF + sw);
                #pragma unroll
                for (int mf = 0; mf < 2; ++mf) {
                    #pragma unroll
                    for (int x = 0; x < 2; ++x) {
                        const int nf = np * 2 + x;
                        hmma(O[mf][nf], pah[mf], vbh[x * 2], vbh[x * 2 + 1]);
                        hmma(O[mf][nf], pal[mf], vbh[x * 2], vbh[x * 2 + 1]);
                        hmma(O[mf][nf], pah[mf], vbl[x * 2], vbl[x * 2 + 1]);
                    }
                }
            }
        }

        __syncthreads();
        if (c + 2 < 32) {
            load_stage((c + 2) * 64, c & 1);
            CP_COMMIT();
            CP_WAIT1();
        } else if (c + 1 < 32) {
            CP_WAIT0();
        }
        __syncthreads();
    }

    // ---- epilogue: normalize, split hi/lo, concat-head layout ----
    const int b = bh >> 4, h = bh & 15;
    const int g = lane >> 2, t = lane & 3;
    #pragma unroll
    for (int mf = 0; mf < 2; ++mf) {
        #pragma unroll
        for (int half = 0; half < 2; ++half) {
            const int idx = mf * 2 + half;
            const float inv = 1.0f / lrow[idx];
            const int srow = q0 + mbase + mf * 16 + half * 8 + g;
            size_t base = ((size_t)(b * S_ + srow)) * D_ + h * 64;
            #pragma unroll
            for (int nf = 0; nf < 8; ++nf) {
                uint32_t lo, hi = packsplit(O[mf][nf][half * 2] * inv,
                                            O[mf][nf][half * 2 + 1] * inv, lo);
                *reinterpret_cast<uint32_t*>(g_Hh + base + nf * 8 + t * 2) = hi;
                *reinterpret_cast<uint32_t*>(g_Hl + base + nf * 8 + t * 2) = lo;
            }
        }
    }
}

// ---------------- launch ----------------
extern "C" void kernel_launch(void* const* d_in, const int* in_sizes, int n_in,
                              void* d_out, int out_size)
{
    const float* q  = (const float*)d_in[0];
    const float* k  = (const float*)d_in[1];
    const float* v  = (const float*)d_in[2];
    const float* Wq = (const float*)d_in[3];
    const float* Wk = (const float*)d_in[4];
    const float* Wv = (const float*)d_in[5];
    const float* Wo = (const float*)d_in[6];
    float* out = (float*)d_out;

    static bool configured = false;
    if (!configured) {
        cudaFuncSetAttribute(mma_gemm, cudaFuncAttributeMaxDynamicSharedMemorySize, MMA_SMEM);
        cudaFuncSetAttribute(attn_mma, cudaFuncAttributeMaxDynamicSharedMemorySize, ATT_SMEM);
        configured = true;
    }

    __nv_bfloat16 *qh, *ql, *kh, *kl, *vh, *vl;
    __nv_bfloat16 *wqh, *wql, *wkh, *wkl, *wvh, *wvl, *woh, *wol, *Hh, *Hl;
    cudaGetSymbolAddress((void**)&qh, g_qh);   cudaGetSymbolAddress((void**)&ql, g_ql);
    cudaGetSymbolAddress((void**)&kh, g_kh);   cudaGetSymbolAddress((void**)&kl, g_kl);
    cudaGetSymbolAddress((void**)&vh, g_vh);   cudaGetSymbolAddress((void**)&vl, g_vl);
    cudaGetSymbolAddress((void**)&wqh, g_wqh); cudaGetSymbolAddress((void**)&wql, g_wql);
    cudaGetSymbolAddress((void**)&wkh, g_wkh); cudaGetSymbolAddress((void**)&wkl, g_wkl);
    cudaGetSymbolAddress((void**)&wvh, g_wvh); cudaGetSymbolAddress((void**)&wvl, g_wvl);
    cudaGetSymbolAddress((void**)&woh, g_woh); cudaGetSymbolAddress((void**)&wol, g_wol);
    cudaGetSymbolAddress((void**)&Hh, g_Hh);   cudaGetSymbolAddress((void**)&Hl, g_Hl);

    conv_in<<<8192, 256>>>(q, qh, ql);
    conv_in<<<8192, 256>>>(k, kh, kl);
    conv_in<<<8192, 256>>>(v, vh, vl);
    conv_w<<<4096, 256>>>(Wq, wqh, wql);
    conv_w<<<4096, 256>>>(Wk, wkh, wkl);
    conv_w<<<4096, 256>>>(Wv, wvh, wvl);
    conv_wo<<<4096, 256>>>(Wo, woh, wol);

    dim3 gemm_grid(H_, M_TOT / 128);     // 16 x 64
    mma_gemm<<<gemm_grid, 128, MMA_SMEM>>>(qh, ql, wqh, wql, nullptr, 0);
    mma_gemm<<<gemm_grid, 128, MMA_SMEM>>>(kh, kl, wkh, wkl, nullptr, 1);
    mma_gemm<<<gemm_grid, 128, MMA_SMEM>>>(vh, vl, wvh, wvl, nullptr, 2);

    dim3 attn_grid(S_ / 128, B_ * H_);   // 16 x 64
    attn_mma<<<attn_grid, 128, ATT_SMEM>>>();

    dim3 out_grid(D_ / 64, M_TOT / 128); // 16 x 64
    mma_gemm<<<out_grid, 128, MMA_SMEM>>>(Hh, Hl, woh, wol, out, 3);
}

// round 6
// speedup vs baseline: 3.7203x; 1.2880x over previous
#include <cuda_runtime.h>
#include <cuda_bf16.h>
#include <cstdint>

#define B_  4
#define S_  2048
#define D_  1024
#define H_  16
#define M_TOT 8192

// ---------------- device scratch (no allocs allowed) ----------------
__device__ __align__(256) __nv_bfloat16 g_qh[M_TOT * D_], g_ql[M_TOT * D_];
__device__ __align__(256) __nv_bfloat16 g_kh[M_TOT * D_], g_kl[M_TOT * D_];
__device__ __align__(256) __nv_bfloat16 g_vh[M_TOT * D_], g_vl[M_TOT * D_];
__device__ __align__(256) __nv_bfloat16 g_wqh[H_ * 64 * D_], g_wql[H_ * 64 * D_];
__device__ __align__(256) __nv_bfloat16 g_wkh[H_ * 64 * D_], g_wkl[H_ * 64 * D_];
__device__ __align__(256) __nv_bfloat16 g_wvh[H_ * 64 * D_], g_wvl[H_ * 64 * D_];
__device__ __align__(256) __nv_bfloat16 g_woh[D_ * D_],     g_wol[D_ * D_];
__device__ __align__(256) __nv_bfloat16 g_Qh[64 * S_ * 64],  g_Ql[64 * S_ * 64];   // [bh][s][dk] (pre-scaled)
__device__ __align__(256) __nv_bfloat16 g_Kh[64 * S_ * 64],  g_Kl[64 * S_ * 64];   // [bh][key][dk]
__device__ __align__(256) __nv_bfloat16 g_Vth[64 * 64 * S_], g_Vtl[64 * 64 * S_];  // [bh][dv][key]
__device__ __align__(256) __nv_bfloat16 g_Hh[M_TOT * D_], g_Hl[M_TOT * D_];

// ---------------- PTX helpers (baseline ISA: sm_80+) ----------------
__device__ __forceinline__ uint32_t smem_u32(const void* p) {
    uint32_t a;
    asm("{ .reg .u64 t; cvta.to.shared.u64 t, %1; cvt.u32.u64 %0, t; }"
        : "=r"(a) : "l"(p));
    return a;
}
__device__ __forceinline__ void cp16(uint32_t dst, const void* src) {
    asm volatile("cp.async.cg.shared.global [%0], [%1], 16;"
                 :: "r"(dst), "l"(src) : "memory");
}
#define CP_COMMIT() asm volatile("cp.async.commit_group;" ::: "memory")
#define CP_WAIT1()  asm volatile("cp.async.wait_group 1;"  ::: "memory")
#define CP_WAIT0()  asm volatile("cp.async.wait_group 0;"  ::: "memory")

__device__ __forceinline__ void ldsm_x4(uint32_t* r, uint32_t addr) {
    asm volatile("ldmatrix.sync.aligned.m8n8.x4.shared.b16 {%0,%1,%2,%3}, [%4];"
                 : "=r"(r[0]), "=r"(r[1]), "=r"(r[2]), "=r"(r[3]) : "r"(addr));
}
__device__ __forceinline__ void hmma(float* d, const uint32_t* a,
                                     uint32_t b0, uint32_t b1) {
    asm volatile("mma.sync.aligned.m16n8k16.row.col.f32.bf16.bf16.f32 "
                 "{%0,%1,%2,%3}, {%4,%5,%6,%7}, {%8,%9}, {%0,%1,%2,%3};"
                 : "+f"(d[0]), "+f"(d[1]), "+f"(d[2]), "+f"(d[3])
                 : "r"(a[0]), "r"(a[1]), "r"(a[2]), "r"(a[3]), "r"(b0), "r"(b1));
}
__device__ __forceinline__ uint32_t swz(uint32_t off) {
    return off ^ ((off >> 3) & 0x70);
}
__device__ __forceinline__ void split_bf16(float x, __nv_bfloat16& h, __nv_bfloat16& l) {
    h = __float2bfloat16(x);
    l = __float2bfloat16(x - __bfloat162float(h));
}
__device__ __forceinline__ uint32_t packsplit(float x, float y, uint32_t& lo) {
    __nv_bfloat16 hx, hy, lx, ly;
    split_bf16(x, hx, lx);
    split_bf16(y, hy, ly);
    __nv_bfloat162 hv = __halves2bfloat162(hx, hy);
    __nv_bfloat162 lv = __halves2bfloat162(lx, ly);
    lo = *reinterpret_cast<uint32_t*>(&lv);
    return *reinterpret_cast<uint32_t*>(&hv);
}

// ---------------- conversion kernels (fused) ----------------
__global__ __launch_bounds__(256) void conv_in3(const float* __restrict__ q,
                                                const float* __restrict__ k,
                                                const float* __restrict__ v)
{
    const int which = blockIdx.y;
    const float* x = (which == 0) ? q : ((which == 1) ? k : v);
    __nv_bfloat16* hi = (which == 0) ? g_qh : ((which == 1) ? g_kh : g_vh);
    __nv_bfloat16* lo = (which == 0) ? g_ql : ((which == 1) ? g_kl : g_vl);
    size_t i = ((size_t)blockIdx.x * 256 + threadIdx.x) * 4;
    float4 vv = *reinterpret_cast<const float4*>(x + i);
    __nv_bfloat16 h0, h1, h2, h3, l0, l1, l2, l3;
    split_bf16(vv.x, h0, l0); split_bf16(vv.y, h1, l1);
    split_bf16(vv.z, h2, l2); split_bf16(vv.w, h3, l3);
    *reinterpret_cast<__nv_bfloat162*>(hi + i)     = __halves2bfloat162(h0, h1);
    *reinterpret_cast<__nv_bfloat162*>(hi + i + 2) = __halves2bfloat162(h2, h3);
    *reinterpret_cast<__nv_bfloat162*>(lo + i)     = __halves2bfloat162(l0, l1);
    *reinterpret_cast<__nv_bfloat162*>(lo + i + 2) = __halves2bfloat162(l2, l3);
}

// W[h][k][n] (16,1024,64) -> Wt[h][n][k] hi/lo, all three weights
__global__ __launch_bounds__(256) void conv_w3(const float* __restrict__ Wq,
                                               const float* __restrict__ Wk,
                                               const float* __restrict__ Wv)
{
    const int which = blockIdx.y;
    const float* W = (which == 0) ? Wq : ((which == 1) ? Wk : Wv);
    __nv_bfloat16* hi = (which == 0) ? g_wqh : ((which == 1) ? g_wkh : g_wvh);
    __nv_bfloat16* lo = (which == 0) ? g_wql : ((which == 1) ? g_wkl : g_wvl);
    int idx = blockIdx.x * 256 + threadIdx.x;        // h*65536 + n*1024 + k
    int k = idx & 1023;
    int n = (idx >> 10) & 63;
    int h = idx >> 16;
    float x = W[((size_t)h * D_ + k) * 64 + n];
    __nv_bfloat16 hh, ll;
    split_bf16(x, hh, ll);
    hi[idx] = hh; lo[idx] = ll;
}

__global__ __launch_bounds__(256) void conv_wo(const float* __restrict__ Wo)
{
    int idx = blockIdx.x * 256 + threadIdx.x;        // n*1024 + k
    int k = idx & 1023;
    int n = idx >> 10;
    float x = Wo[(size_t)k * D_ + n];
    __nv_bfloat16 hh, ll;
    split_bf16(x, hh, ll);
    g_woh[idx] = hh; g_wol[idx] = ll;
}

// ---------------- split-bf16 HMMA GEMM (256 thr, 8 warps x 16 rows) ----------------
#define STAGE_BYTES 49152
#define A_HI_OFF 0
#define A_LO_OFF 16384
#define B_HI_OFF 32768
#define B_LO_OFF 40960
#define MMA_SMEM (2 * STAGE_BYTES)

__global__ __launch_bounds__(256) void mma_gemm(const __nv_bfloat16* __restrict__ ah,
                                                const __nv_bfloat16* __restrict__ al,
                                                const __nv_bfloat16* __restrict__ bh,
                                                const __nv_bfloat16* __restrict__ bl,
                                                float* __restrict__ outp, int mode)
{
    extern __shared__ char sm[];
    const uint32_t smem = smem_u32(sm);
    const int tid  = threadIdx.x;
    const int wid  = tid >> 5;
    const int lane = tid & 31;
    const int nb   = blockIdx.x;
    const int m0   = blockIdx.y * 128;
    const int mbase = wid * 16;

    const __nv_bfloat16* aH = ah + (size_t)m0 * D_;
    const __nv_bfloat16* aL = al + (size_t)m0 * D_;
    const __nv_bfloat16* bH = bh + (size_t)nb * 64 * D_;
    const __nv_bfloat16* bL = bl + (size_t)nb * 64 * D_;

    // loaders: A 128 rows x 128B (2 thr/row, 4x16B each); B 64 rows (4 thr/row, 2x16B)
    const int arow = tid >> 1, ahalf = tid & 1;
    const int brow_ = tid >> 2, bq = tid & 3;
    auto load_stage = [&](int c, int buf) {
        const uint32_t sb = smem + buf * STAGE_BYTES;
        const int k0 = c * 64;
        const char* gh = (const char*)(aH + (size_t)arow * D_ + k0) + ahalf * 64;
        const char* gl = (const char*)(aL + (size_t)arow * D_ + k0) + ahalf * 64;
        #pragma unroll
        for (int j = 0; j < 4; ++j) {
            uint32_t sw = swz(arow * 128 + ahalf * 64 + j * 16);
            cp16(sb + A_HI_OFF + sw, gh + j * 16);
            cp16(sb + A_LO_OFF + sw, gl + j * 16);
        }
        const char* gbh = (const char*)(bH + (size_t)brow_ * D_ + k0) + bq * 32;
        const char* gbl = (const char*)(bL + (size_t)brow_ * D_ + k0) + bq * 32;
        #pragma unroll
        for (int j = 0; j < 2; ++j) {
            uint32_t sw = swz(brow_ * 128 + bq * 32 + j * 16);
            cp16(sb + B_HI_OFF + sw, gbh + j * 16);
            cp16(sb + B_LO_OFF + sw, gbl + j * 16);
        }
    };

    float acc[8][4] = {};

    load_stage(0, 0);
    CP_COMMIT();

    for (int c = 0; c < 16; ++c) {
        const int buf = c & 1;
        if (c < 15) { load_stage(c + 1, buf ^ 1); CP_COMMIT(); }
        if (c < 15) CP_WAIT1(); else CP_WAIT0();
        __syncthreads();

        const uint32_t sb = smem + buf * STAGE_BYTES;
        #pragma unroll
        for (int ks = 0; ks < 4; ++ks) {
            const int kb = ks * 32;
            uint32_t ahi[4], alo[4];
            {
                uint32_t off = (uint32_t)(mbase + (lane & 15)) * 128
                             + kb + (lane >> 4) * 16;
                uint32_t sw = swz(off);
                ldsm_x4(ahi, sb + A_HI_OFF + sw);
                ldsm_x4(alo, sb + A_LO_OFF + sw);
            }
            uint32_t bhi[4][4], blo[4][4];
            #pragma unroll
            for (int np = 0; np < 4; ++np) {
                uint32_t n  = np * 16 + (lane & 7) + ((lane >> 4) << 3);
                uint32_t off = n * 128 + kb + ((lane >> 3) & 1) * 16;
                uint32_t sw = swz(off);
                ldsm_x4(bhi[np], sb + B_HI_OFF + sw);
                ldsm_x4(blo[np], sb + B_LO_OFF + sw);
            }
            #pragma unroll
            for (int nf = 0; nf < 8; ++nf) {
                const int np = nf >> 1, sel = (nf & 1) * 2;
                hmma(acc[nf], ahi, bhi[np][sel], bhi[np][sel + 1]);
                hmma(acc[nf], ahi, blo[np][sel], blo[np][sel + 1]);
                hmma(acc[nf], alo, bhi[np][sel], bhi[np][sel + 1]);
            }
        }
        __syncthreads();
    }

    // ---- epilogue ----
    const int g = lane >> 2;
    const int t = lane & 3;
    #pragma unroll
    for (int half = 0; half < 2; ++half) {
        const int m = m0 + mbase + half * 8 + g;
        if (mode == 3) {
            float* orow = outp + (size_t)m * D_ + nb * 64;
            #pragma unroll
            for (int nf = 0; nf < 8; ++nf)
                *reinterpret_cast<float2*>(orow + nf * 8 + t * 2) =
                    make_float2(acc[nf][half * 2], acc[nf][half * 2 + 1]);
        } else {
            const int b = m >> 11, s = m & (S_ - 1);
            const int bh_ = b * H_ + nb;
            if (mode < 2) {
                const float sc = (mode == 0) ? 0.125f : 1.0f;
                __nv_bfloat16* dh = (mode == 0) ? g_Qh : g_Kh;
                __nv_bfloat16* dl = (mode == 0) ? g_Ql : g_Kl;
                size_t base = ((size_t)bh_ * S_ + s) * 64;
                #pragma unroll
                for (int nf = 0; nf < 8; ++nf) {
                    uint32_t lo, hi = packsplit(acc[nf][half * 2] * sc,
                                                acc[nf][half * 2 + 1] * sc, lo);
                    *reinterpret_cast<uint32_t*>(dh + base + nf * 8 + t * 2) = hi;
                    *reinterpret_cast<uint32_t*>(dl + base + nf * 8 + t * 2) = lo;
                }
            } else {
                #pragma unroll
                for (int nf = 0; nf < 8; ++nf) {
                    #pragma unroll
                    for (int e = 0; e < 2; ++e) {
                        int dv = nf * 8 + t * 2 + e;
                        __nv_bfloat16 hh, ll;
                        split_bf16(acc[nf][half * 2 + e], hh, ll);
                        size_t addr = ((size_t)bh_ * 64 + dv) * S_ + s;
                        g_Vth[addr] = hh;
                        g_Vtl[addr] = ll;
                    }
                }
            }
        }
    }
}

// ---------------- tensor-core flash attention (256 thr, 8 warps x 16 q-rows) ----------------
#define KH_OFF 0
#define KL_OFF 8192
#define VH_OFF 16384
#define VL_OFF 24576
#define AT_STAGE 32768
#define QH_OFF 65536
#define QL_OFF (65536 + 16384)
#define ATT_SMEM 98304

__global__ __launch_bounds__(256) void attn_mma()
{
    extern __shared__ char sm[];
    const uint32_t smem = smem_u32(sm);
    const int tid  = threadIdx.x;
    const int wid  = tid >> 5;
    const int lane = tid & 31;
    const int bh   = blockIdx.y;
    const int q0   = blockIdx.x * 128;
    const int mbase = wid * 16;

    // Q tile async load (128 rows x 128B hi/lo; 2 thr/row, 4x16B)
    {
        const int row = tid >> 1, half = tid & 1;
        const char* gh = (const char*)(g_Qh + ((size_t)bh * S_ + q0 + row) * 64) + half * 64;
        const char* gl = (const char*)(g_Ql + ((size_t)bh * S_ + q0 + row) * 64) + half * 64;
        #pragma unroll
        for (int i = 0; i < 4; ++i) {
            uint32_t sw = swz(row * 128 + half * 64 + i * 16);
            cp16(smem + QH_OFF + sw, gh + i * 16);
            cp16(smem + QL_OFF + sw, gl + i * 16);
        }
    }
    const int r4 = tid >> 2, qq = tid & 3;
    auto load_stage = [&](int kt, int buf) {
        const uint32_t sb = smem + buf * AT_STAGE;
        const char* kh = (const char*)(g_Kh + ((size_t)bh * S_ + kt + r4) * 64) + qq * 32;
        const char* kl = (const char*)(g_Kl + ((size_t)bh * S_ + kt + r4) * 64) + qq * 32;
        const char* vh = (const char*)(g_Vth + ((size_t)bh * 64 + r4) * S_ + kt) + qq * 32;
        const char* vl = (const char*)(g_Vtl + ((size_t)bh * 64 + r4) * S_ + kt) + qq * 32;
        #pragma unroll
        for (int j = 0; j < 2; ++j) {
            uint32_t sw = swz(r4 * 128 + qq * 32 + j * 16);
            cp16(sb + KH_OFF + sw, kh + j * 16);
            cp16(sb + KL_OFF + sw, kl + j * 16);
            cp16(sb + VH_OFF + sw, vh + j * 16);
            cp16(sb + VL_OFF + sw, vl + j * 16);
        }
    };
    load_stage(0, 0);  CP_COMMIT();
    load_stage(64, 1); CP_COMMIT();
    CP_WAIT1();
    __syncthreads();

    // persistent Q hi fragments; Q lo re-loaded per use
    uint32_t qh[4][4];
    #pragma unroll
    for (int ks = 0; ks < 4; ++ks) {
        uint32_t off = (uint32_t)(mbase + (lane & 15)) * 128
                     + ks * 32 + (lane >> 4) * 16;
        ldsm_x4(qh[ks], smem + QH_OFF + swz(off));
    }

    float O[8][4] = {};
    float mrow[2] = {-1e30f, -1e30f};
    float lrow[2] = {};

    for (int c = 0; c < 32; ++c) {
        const uint32_t sb = smem + (c & 1) * AT_STAGE;

        // ---- QK^T (3-MMA split) ----
        float s[8][4] = {};
        #pragma unroll
        for (int ks = 0; ks < 4; ++ks) {
            uint32_t ql_[4];
            {
                uint32_t off = (uint32_t)(mbase + (lane & 15)) * 128
                             + ks * 32 + (lane >> 4) * 16;
                ldsm_x4(ql_, smem + QL_OFF + swz(off));
            }
            #pragma unroll
            for (int np = 0; np < 4; ++np) {
                uint32_t n  = np * 16 + (lane & 7) + ((lane >> 4) << 3);
                uint32_t off = n * 128 + ks * 32 + ((lane >> 3) & 1) * 16;
                uint32_t sw = swz(off);
                uint32_t kbh[4], kbl[4];
                ldsm_x4(kbh, sb + KH_OFF + sw);
                ldsm_x4(kbl, sb + KL_OFF + sw);
                #pragma unroll
                for (int x = 0; x < 2; ++x) {
                    const int nf = np * 2 + x;
                    hmma(s[nf], qh[ks], kbh[x * 2], kbh[x * 2 + 1]);
                    hmma(s[nf], qh[ks], kbl[x * 2], kbl[x * 2 + 1]);
                    hmma(s[nf], ql_,    kbh[x * 2], kbh[x * 2 + 1]);
                }
            }
        }

        // ---- online softmax on fragments ----
        #pragma unroll
        for (int half = 0; half < 2; ++half) {
            float rmax = -1e30f;
            #pragma unroll
            for (int nf = 0; nf < 8; ++nf)
                rmax = fmaxf(rmax, fmaxf(s[nf][half * 2], s[nf][half * 2 + 1]));
            rmax = fmaxf(rmax, __shfl_xor_sync(0xffffffffu, rmax, 1));
            rmax = fmaxf(rmax, __shfl_xor_sync(0xffffffffu, rmax, 2));
            const float mnew = fmaxf(mrow[half], rmax);
            const float corr = __expf(mrow[half] - mnew);
            float rsum = 0.0f;
            #pragma unroll
            for (int nf = 0; nf < 8; ++nf) {
                float p0 = __expf(s[nf][half * 2]     - mnew);
                float p1 = __expf(s[nf][half * 2 + 1] - mnew);
                s[nf][half * 2]     = p0;
                s[nf][half * 2 + 1] = p1;
                rsum += p0 + p1;
            }
            rsum += __shfl_xor_sync(0xffffffffu, rsum, 1);
            rsum += __shfl_xor_sync(0xffffffffu, rsum, 2);
            lrow[half] = lrow[half] * corr + rsum;
            mrow[half] = mnew;
            #pragma unroll
            for (int nf = 0; nf < 8; ++nf) {
                O[nf][half * 2]     *= corr;
                O[nf][half * 2 + 1] *= corr;
            }
        }

        // ---- P @ V (3-MMA split; P frags repacked from accum regs) ----
        #pragma unroll
        for (int kk = 0; kk < 4; ++kk) {
            uint32_t pah[4], pal[4];
            pah[0] = packsplit(s[2 * kk][0],     s[2 * kk][1],     pal[0]);
            pah[1] = packsplit(s[2 * kk][2],     s[2 * kk][3],     pal[1]);
            pah[2] = packsplit(s[2 * kk + 1][0], s[2 * kk + 1][1], pal[2]);
            pah[3] = packsplit(s[2 * kk + 1][2], s[2 * kk + 1][3], pal[3]);
            #pragma unroll
            for (int np = 0; np < 4; ++np) {
                uint32_t n  = np * 16 + (lane & 7) + ((lane >> 4) << 3);
                uint32_t off = n * 128 + kk * 32 + ((lane >> 3) & 1) * 16;
                uint32_t sw = swz(off);
                uint32_t vbh[4], vbl[4];
                ldsm_x4(vbh, sb + VH_OFF + sw);
                ldsm_x4(vbl, sb + VL_OFF + sw);
                #pragma unroll
                for (int x = 0; x < 2; ++x) {
                    const int nf = np * 2 + x;
                    hmma(O[nf], pah, vbh[x * 2], vbh[x * 2 + 1]);
                    hmma(O[nf], pal, vbh[x * 2], vbh[x * 2 + 1]);
                    hmma(O[nf], pah, vbl[x * 2], vbl[x * 2 + 1]);
                }
            }
        }

        __syncthreads();
        if (c + 2 < 32) {
            load_stage((c + 2) * 64, c & 1);
            CP_COMMIT();
            CP_WAIT1();
        } else if (c + 1 < 32) {
            CP_WAIT0();
        }
        __syncthreads();
    }

    // ---- epilogue: normalize, split hi/lo, concat-head layout ----
    const int b = bh >> 4, h = bh & 15;
    const int g = lane >> 2, t = lane & 3;
    #pragma unroll
    for (int half = 0; half < 2; ++half) {
        const float inv = 1.0f / lrow[half];
        const int srow = q0 + mbase + half * 8 + g;
        size_t base = ((size_t)(b * S_ + srow)) * D_ + h * 64;
        #pragma unroll
        for (int nf = 0; nf < 8; ++nf) {
            uint32_t lo, hi = packsplit(O[nf][half * 2] * inv,
                                        O[nf][half * 2 + 1] * inv, lo);
            *reinterpret_cast<uint32_t*>(g_Hh + base + nf * 8 + t * 2) = hi;
            *reinterpret_cast<uint32_t*>(g_Hl + base + nf * 8 + t * 2) = lo;
        }
    }
}

// ---------------- launch ----------------
extern "C" void kernel_launch(void* const* d_in, const int* in_sizes, int n_in,
                              void* d_out, int out_size)
{
    const float* q  = (const float*)d_in[0];
    const float* k  = (const float*)d_in[1];
    const float* v  = (const float*)d_in[2];
    const float* Wq = (const float*)d_in[3];
    const float* Wk = (const float*)d_in[4];
    const float* Wv = (const float*)d_in[5];
    const float* Wo = (const float*)d_in[6];
    float* out = (float*)d_out;

    static bool configured = false;
    if (!configured) {
        cudaFuncSetAttribute(mma_gemm, cudaFuncAttributeMaxDynamicSharedMemorySize, MMA_SMEM);
        cudaFuncSetAttribute(attn_mma, cudaFuncAttributeMaxDynamicSharedMemorySize, ATT_SMEM);
        configured = true;
    }

    __nv_bfloat16 *qh, *ql, *kh, *kl, *vh, *vl;
    __nv_bfloat16 *wqh, *wql, *wkh, *wkl, *wvh, *wvl, *woh, *wol, *Hh, *Hl;
    cudaGetSymbolAddress((void**)&qh, g_qh);   cudaGetSymbolAddress((void**)&ql, g_ql);
    cudaGetSymbolAddress((void**)&kh, g_kh);   cudaGetSymbolAddress((void**)&kl, g_kl);
    cudaGetSymbolAddress((void**)&vh, g_vh);   cudaGetSymbolAddress((void**)&vl, g_vl);
    cudaGetSymbolAddress((void**)&wqh, g_wqh); cudaGetSymbolAddress((void**)&wql, g_wql);
    cudaGetSymbolAddress((void**)&wkh, g_wkh); cudaGetSymbolAddress((void**)&wkl, g_wkl);
    cudaGetSymbolAddress((void**)&wvh, g_wvh); cudaGetSymbolAddress((void**)&wvl, g_wvl);
    cudaGetSymbolAddress((void**)&woh, g_woh); cudaGetSymbolAddress((void**)&wol, g_wol);
    cudaGetSymbolAddress((void**)&Hh, g_Hh);   cudaGetSymbolAddress((void**)&Hl, g_Hl);

    // launches 1-3: conversions; launch 6 (profiled by -s 5 -c 1) = Q projection GEMM
    conv_in3<<<dim3(8192, 3), 256>>>(q, k, v);
    conv_w3<<<dim3(4096, 3), 256>>>(Wq, Wk, Wv);
    conv_wo<<<4096, 256>>>(Wo);

    dim3 gemm_grid(H_, M_TOT / 128);     // 16 x 64
    mma_gemm<<<gemm_grid, 256, MMA_SMEM>>>(vh, vl, wvh, wvl, nullptr, 2);
    mma_gemm<<<gemm_grid, 256, MMA_SMEM>>>(kh, kl, wkh, wkl, nullptr, 1);
    mma_gemm<<<gemm_grid, 256, MMA_SMEM>>>(qh, ql, wqh, wql, nullptr, 0);

    dim3 attn_grid(S_ / 128, B_ * H_);   // 16 x 64
    attn_mma<<<attn_grid, 256, ATT_SMEM>>>();

    dim3 out_grid(D_ / 64, M_TOT / 128); // 16 x 64
    mma_gemm<<<out_grid, 256, MMA_SMEM>>>(Hh, Hl, woh, wol, out, 3);
}

// round 7
// speedup vs baseline: 3.7442x; 1.0064x over previous
#include <cuda_runtime.h>
#include <cuda_bf16.h>
#include <cstdint>

#define B_  4
#define S_  2048
#define D_  1024
#define H_  16
#define M_TOT 8192

// ---------------- device scratch (no allocs allowed) ----------------
__device__ __align__(256) __nv_bfloat16 g_qh[M_TOT * D_], g_ql[M_TOT * D_];
__device__ __align__(256) __nv_bfloat16 g_kh[M_TOT * D_], g_kl[M_TOT * D_];
__device__ __align__(256) __nv_bfloat16 g_vh[M_TOT * D_], g_vl[M_TOT * D_];
__device__ __align__(256) __nv_bfloat16 g_wqh[H_ * 64 * D_], g_wql[H_ * 64 * D_];
__device__ __align__(256) __nv_bfloat16 g_wkh[H_ * 64 * D_], g_wkl[H_ * 64 * D_];
__device__ __align__(256) __nv_bfloat16 g_wvh[H_ * 64 * D_], g_wvl[H_ * 64 * D_];
__device__ __align__(256) __nv_bfloat16 g_woh[D_ * D_],     g_wol[D_ * D_];
__device__ __align__(256) __nv_bfloat16 g_Qh[64 * S_ * 64],  g_Ql[64 * S_ * 64];   // [bh][s][dk] (pre-scaled)
__device__ __align__(256) __nv_bfloat16 g_Kh[64 * S_ * 64],  g_Kl[64 * S_ * 64];   // [bh][key][dk]
__device__ __align__(256) __nv_bfloat16 g_Vth[64 * 64 * S_], g_Vtl[64 * 64 * S_];  // [bh][dv][key]
__device__ __align__(256) __nv_bfloat16 g_Hh[M_TOT * D_], g_Hl[M_TOT * D_];

// ---------------- PTX helpers (baseline ISA: sm_80+) ----------------
__device__ __forceinline__ uint32_t smem_u32(const void* p) {
    uint32_t a;
    asm("{ .reg .u64 t; cvta.to.shared.u64 t, %1; cvt.u32.u64 %0, t; }"
        : "=r"(a) : "l"(p));
    return a;
}
__device__ __forceinline__ void cp16(uint32_t dst, const void* src) {
    asm volatile("cp.async.cg.shared.global [%0], [%1], 16;"
                 :: "r"(dst), "l"(src) : "memory");
}
#define CP_COMMIT() asm volatile("cp.async.commit_group;" ::: "memory")
#define CP_WAIT1()  asm volatile("cp.async.wait_group 1;"  ::: "memory")
#define CP_WAIT0()  asm volatile("cp.async.wait_group 0;"  ::: "memory")

__device__ __forceinline__ void ldsm_x4(uint32_t* r, uint32_t addr) {
    asm volatile("ldmatrix.sync.aligned.m8n8.x4.shared.b16 {%0,%1,%2,%3}, [%4];"
                 : "=r"(r[0]), "=r"(r[1]), "=r"(r[2]), "=r"(r[3]) : "r"(addr));
}
__device__ __forceinline__ void hmma(float* d, const uint32_t* a,
                                     uint32_t b0, uint32_t b1) {
    asm volatile("mma.sync.aligned.m16n8k16.row.col.f32.bf16.bf16.f32 "
                 "{%0,%1,%2,%3}, {%4,%5,%6,%7}, {%8,%9}, {%0,%1,%2,%3};"
                 : "+f"(d[0]), "+f"(d[1]), "+f"(d[2]), "+f"(d[3])
                 : "r"(a[0]), "r"(a[1]), "r"(a[2]), "r"(a[3]), "r"(b0), "r"(b1));
}
__device__ __forceinline__ uint32_t swz(uint32_t off) {
    return off ^ ((off >> 3) & 0x70);
}
__device__ __forceinline__ void split_bf16(float x, __nv_bfloat16& h, __nv_bfloat16& l) {
    h = __float2bfloat16(x);
    l = __float2bfloat16(x - __bfloat162float(h));
}
__device__ __forceinline__ uint32_t packsplit(float x, float y, uint32_t& lo) {
    __nv_bfloat16 hx, hy, lx, ly;
    split_bf16(x, hx, lx);
    split_bf16(y, hy, ly);
    __nv_bfloat162 hv = __halves2bfloat162(hx, hy);
    __nv_bfloat162 lv = __halves2bfloat162(lx, ly);
    lo = *reinterpret_cast<uint32_t*>(&lv);
    return *reinterpret_cast<uint32_t*>(&hv);
}

// ---------------- conversion kernels (fused) ----------------
__global__ __launch_bounds__(256) void conv_in3(const float* __restrict__ q,
                                                const float* __restrict__ k,
                                                const float* __restrict__ v)
{
    const int which = blockIdx.y;
    const float* x = (which == 0) ? q : ((which == 1) ? k : v);
    __nv_bfloat16* hi = (which == 0) ? g_qh : ((which == 1) ? g_kh : g_vh);
    __nv_bfloat16* lo = (which == 0) ? g_ql : ((which == 1) ? g_kl : g_vl);
    size_t i = ((size_t)blockIdx.x * 256 + threadIdx.x) * 4;
    float4 vv = *reinterpret_cast<const float4*>(x + i);
    __nv_bfloat16 h0, h1, h2, h3, l0, l1, l2, l3;
    split_bf16(vv.x, h0, l0); split_bf16(vv.y, h1, l1);
    split_bf16(vv.z, h2, l2); split_bf16(vv.w, h3, l3);
    *reinterpret_cast<__nv_bfloat162*>(hi + i)     = __halves2bfloat162(h0, h1);
    *reinterpret_cast<__nv_bfloat162*>(hi + i + 2) = __halves2bfloat162(h2, h3);
    *reinterpret_cast<__nv_bfloat162*>(lo + i)     = __halves2bfloat162(l0, l1);
    *reinterpret_cast<__nv_bfloat162*>(lo + i + 2) = __halves2bfloat162(l2, l3);
}

// W[h][k][n] (16,1024,64) -> Wt[h][n][k] hi/lo, all three weights
__global__ __launch_bounds__(256) void conv_w3(const float* __restrict__ Wq,
                                               const float* __restrict__ Wk,
                                               const float* __restrict__ Wv)
{
    const int which = blockIdx.y;
    const float* W = (which == 0) ? Wq : ((which == 1) ? Wk : Wv);
    __nv_bfloat16* hi = (which == 0) ? g_wqh : ((which == 1) ? g_wkh : g_wvh);
    __nv_bfloat16* lo = (which == 0) ? g_wql : ((which == 1) ? g_wkl : g_wvl);
    int idx = blockIdx.x * 256 + threadIdx.x;        // h*65536 + n*1024 + k
    int k = idx & 1023;
    int n = (idx >> 10) & 63;
    int h = idx >> 16;
    float x = W[((size_t)h * D_ + k) * 64 + n];
    __nv_bfloat16 hh, ll;
    split_bf16(x, hh, ll);
    hi[idx] = hh; lo[idx] = ll;
}

__global__ __launch_bounds__(256) void conv_wo(const float* __restrict__ Wo)
{
    int idx = blockIdx.x * 256 + threadIdx.x;        // n*1024 + k
    int k = idx & 1023;
    int n = idx >> 10;
    float x = Wo[(size_t)k * D_ + n];
    __nv_bfloat16 hh, ll;
    split_bf16(x, hh, ll);
    g_woh[idx] = hh; g_wol[idx] = ll;
}

// ---------------- split-bf16 HMMA GEMM (256 thr, 8 warps x 16 rows) ----------------
#define STAGE_BYTES 49152
#define A_HI_OFF 0
#define A_LO_OFF 16384
#define B_HI_OFF 32768
#define B_LO_OFF 40960
#define MMA_SMEM (2 * STAGE_BYTES)

__global__ __launch_bounds__(256) void mma_gemm(const __nv_bfloat16* __restrict__ ah,
                                                const __nv_bfloat16* __restrict__ al,
                                                const __nv_bfloat16* __restrict__ bh,
                                                const __nv_bfloat16* __restrict__ bl,
                                                float* __restrict__ outp, int mode)
{
    extern __shared__ char sm[];
    const uint32_t smem = smem_u32(sm);
    const int tid  = threadIdx.x;
    const int wid  = tid >> 5;
    const int lane = tid & 31;
    const int nb   = blockIdx.x;
    const int m0   = blockIdx.y * 128;
    const int mbase = wid * 16;

    const __nv_bfloat16* aH = ah + (size_t)m0 * D_;
    const __nv_bfloat16* aL = al + (size_t)m0 * D_;
    const __nv_bfloat16* bH = bh + (size_t)nb * 64 * D_;
    const __nv_bfloat16* bL = bl + (size_t)nb * 64 * D_;

    const int arow = tid >> 1, ahalf = tid & 1;
    const int brow_ = tid >> 2, bq = tid & 3;
    auto load_stage = [&](int c, int buf) {
        const uint32_t sb = smem + buf * STAGE_BYTES;
        const int k0 = c * 64;
        const char* gh = (const char*)(aH + (size_t)arow * D_ + k0) + ahalf * 64;
        const char* gl = (const char*)(aL + (size_t)arow * D_ + k0) + ahalf * 64;
        #pragma unroll
        for (int j = 0; j < 4; ++j) {
            uint32_t sw = swz(arow * 128 + ahalf * 64 + j * 16);
            cp16(sb + A_HI_OFF + sw, gh + j * 16);
            cp16(sb + A_LO_OFF + sw, gl + j * 16);
        }
        const char* gbh = (const char*)(bH + (size_t)brow_ * D_ + k0) + bq * 32;
        const char* gbl = (const char*)(bL + (size_t)brow_ * D_ + k0) + bq * 32;
        #pragma unroll
        for (int j = 0; j < 2; ++j) {
            uint32_t sw = swz(brow_ * 128 + bq * 32 + j * 16);
            cp16(sb + B_HI_OFF + sw, gbh + j * 16);
            cp16(sb + B_LO_OFF + sw, gbl + j * 16);
        }
    };

    float acc[8][4] = {};

    load_stage(0, 0);
    CP_COMMIT();

    for (int c = 0; c < 16; ++c) {
        const int buf = c & 1;
        if (c < 15) { load_stage(c + 1, buf ^ 1); CP_COMMIT(); }
        if (c < 15) CP_WAIT1(); else CP_WAIT0();
        __syncthreads();

        const uint32_t sb = smem + buf * STAGE_BYTES;
        #pragma unroll
        for (int ks = 0; ks < 4; ++ks) {
            const int kb = ks * 32;
            uint32_t ahi[4], alo[4];
            {
                uint32_t off = (uint32_t)(mbase + (lane & 15)) * 128
                             + kb + (lane >> 4) * 16;
                uint32_t sw = swz(off);
                ldsm_x4(ahi, sb + A_HI_OFF + sw);
                ldsm_x4(alo, sb + A_LO_OFF + sw);
            }
            uint32_t bhi[4][4], blo[4][4];
            #pragma unroll
            for (int np = 0; np < 4; ++np) {
                uint32_t n  = np * 16 + (lane & 7) + ((lane >> 4) << 3);
                uint32_t off = n * 128 + kb + ((lane >> 3) & 1) * 16;
                uint32_t sw = swz(off);
                ldsm_x4(bhi[np], sb + B_HI_OFF + sw);
                ldsm_x4(blo[np], sb + B_LO_OFF + sw);
            }
            // term-major: consecutive HMMAs hit independent accumulators (gap 8)
            #pragma unroll
            for (int nf = 0; nf < 8; ++nf) {
                const int np = nf >> 1, sel = (nf & 1) * 2;
                hmma(acc[nf], ahi, bhi[np][sel], bhi[np][sel + 1]);
            }
            #pragma unroll
            for (int nf = 0; nf < 8; ++nf) {
                const int np = nf >> 1, sel = (nf & 1) * 2;
                hmma(acc[nf], ahi, blo[np][sel], blo[np][sel + 1]);
            }
            #pragma unroll
            for (int nf = 0; nf < 8; ++nf) {
                const int np = nf >> 1, sel = (nf & 1) * 2;
                hmma(acc[nf], alo, bhi[np][sel], bhi[np][sel + 1]);
            }
        }
        __syncthreads();
    }

    // ---- epilogue ----
    const int g = lane >> 2;
    const int t = lane & 3;
    #pragma unroll
    for (int half = 0; half < 2; ++half) {
        const int m = m0 + mbase + half * 8 + g;
        if (mode == 3) {
            float* orow = outp + (size_t)m * D_ + nb * 64;
            #pragma unroll
            for (int nf = 0; nf < 8; ++nf)
                *reinterpret_cast<float2*>(orow + nf * 8 + t * 2) =
                    make_float2(acc[nf][half * 2], acc[nf][half * 2 + 1]);
        } else {
            const int b = m >> 11, s = m & (S_ - 1);
            const int bh_ = b * H_ + nb;
            if (mode < 2) {
                const float sc = (mode == 0) ? 0.125f : 1.0f;
                __nv_bfloat16* dh = (mode == 0) ? g_Qh : g_Kh;
                __nv_bfloat16* dl = (mode == 0) ? g_Ql : g_Kl;
                size_t base = ((size_t)bh_ * S_ + s) * 64;
                #pragma unroll
                for (int nf = 0; nf < 8; ++nf) {
                    uint32_t lo, hi = packsplit(acc[nf][half * 2] * sc,
                                                acc[nf][half * 2 + 1] * sc, lo);
                    *reinterpret_cast<uint32_t*>(dh + base + nf * 8 + t * 2) = hi;
                    *reinterpret_cast<uint32_t*>(dl + base + nf * 8 + t * 2) = lo;
                }
            } else {
                #pragma unroll
                for (int nf = 0; nf < 8; ++nf) {
                    #pragma unroll
                    for (int e = 0; e < 2; ++e) {
                        int dv = nf * 8 + t * 2 + e;
                        __nv_bfloat16 hh, ll;
                        split_bf16(acc[nf][half * 2 + e], hh, ll);
                        size_t addr = ((size_t)bh_ * 64 + dv) * S_ + s;
                        g_Vth[addr] = hh;
                        g_Vtl[addr] = ll;
                    }
                }
            }
        }
    }
}

// ---------------- tensor-core flash attention (256 thr, 8 warps x 16 q-rows) ----------------
#define KH_OFF 0
#define KL_OFF 8192
#define VH_OFF 16384
#define VL_OFF 24576
#define AT_STAGE 32768
#define QH_OFF 65536
#define QL_OFF (65536 + 16384)
#define ATT_SMEM 98304

__global__ __launch_bounds__(256) void attn_mma()
{
    extern __shared__ char sm[];
    const uint32_t smem = smem_u32(sm);
    const int tid  = threadIdx.x;
    const int wid  = tid >> 5;
    const int lane = tid & 31;
    const int bh   = blockIdx.y;
    const int q0   = blockIdx.x * 128;
    const int mbase = wid * 16;

    // Q tile async load
    {
        const int row = tid >> 1, half = tid & 1;
        const char* gh = (const char*)(g_Qh + ((size_t)bh * S_ + q0 + row) * 64) + half * 64;
        const char* gl = (const char*)(g_Ql + ((size_t)bh * S_ + q0 + row) * 64) + half * 64;
        #pragma unroll
        for (int i = 0; i < 4; ++i) {
            uint32_t sw = swz(row * 128 + half * 64 + i * 16);
            cp16(smem + QH_OFF + sw, gh + i * 16);
            cp16(smem + QL_OFF + sw, gl + i * 16);
        }
    }
    const int r4 = tid >> 2, qq = tid & 3;
    auto load_stage = [&](int kt, int buf) {
        const uint32_t sb = smem + buf * AT_STAGE;
        const char* kh = (const char*)(g_Kh + ((size_t)bh * S_ + kt + r4) * 64) + qq * 32;
        const char* kl = (const char*)(g_Kl + ((size_t)bh * S_ + kt + r4) * 64) + qq * 32;
        const char* vh = (const char*)(g_Vth + ((size_t)bh * 64 + r4) * S_ + kt) + qq * 32;
        const char* vl = (const char*)(g_Vtl + ((size_t)bh * 64 + r4) * S_ + kt) + qq * 32;
        #pragma unroll
        for (int j = 0; j < 2; ++j) {
            uint32_t sw = swz(r4 * 128 + qq * 32 + j * 16);
            cp16(sb + KH_OFF + sw, kh + j * 16);
            cp16(sb + KL_OFF + sw, kl + j * 16);
            cp16(sb + VH_OFF + sw, vh + j * 16);
            cp16(sb + VL_OFF + sw, vl + j * 16);
        }
    };
    load_stage(0, 0);  CP_COMMIT();
    load_stage(64, 1); CP_COMMIT();
    CP_WAIT1();
    __syncthreads();

    // persistent Q hi fragments; Q lo re-loaded per use
    uint32_t qh[4][4];
    #pragma unroll
    for (int ks = 0; ks < 4; ++ks) {
        uint32_t off = (uint32_t)(mbase + (lane & 15)) * 128
                     + ks * 32 + (lane >> 4) * 16;
        ldsm_x4(qh[ks], smem + QH_OFF + swz(off));
    }

    float O[8][4] = {};
    float mrow[2] = {-1e30f, -1e30f};
    float lrow[2] = {};

    for (int c = 0; c < 32; ++c) {
        const uint32_t sb = smem + (c & 1) * AT_STAGE;

        // ---- QK^T (3-MMA split, term-major in np-pairs: dep gap 4) ----
        float s[8][4] = {};
        #pragma unroll
        for (int ks = 0; ks < 4; ++ks) {
            uint32_t ql_[4];
            {
                uint32_t off = (uint32_t)(mbase + (lane & 15)) * 128
                             + ks * 32 + (lane >> 4) * 16;
                ldsm_x4(ql_, smem + QL_OFF + swz(off));
            }
            #pragma unroll
            for (int np2 = 0; np2 < 2; ++np2) {
                uint32_t kbh2[2][4], kbl2[2][4];
                #pragma unroll
                for (int j = 0; j < 2; ++j) {
                    const int np = np2 * 2 + j;
                    uint32_t n  = np * 16 + (lane & 7) + ((lane >> 4) << 3);
                    uint32_t off = n * 128 + ks * 32 + ((lane >> 3) & 1) * 16;
                    uint32_t sw = swz(off);
                    ldsm_x4(kbh2[j], sb + KH_OFF + sw);
                    ldsm_x4(kbl2[j], sb + KL_OFF + sw);
                }
                #pragma unroll
                for (int j = 0; j < 4; ++j) {
                    const int p = j >> 1, sel = (j & 1) * 2;
                    hmma(s[np2 * 4 + j], qh[ks], kbh2[p][sel], kbh2[p][sel + 1]);
                }
                #pragma unroll
                for (int j = 0; j < 4; ++j) {
                    const int p = j >> 1, sel = (j & 1) * 2;
                    hmma(s[np2 * 4 + j], qh[ks], kbl2[p][sel], kbl2[p][sel + 1]);
                }
                #pragma unroll
                for (int j = 0; j < 4; ++j) {
                    const int p = j >> 1, sel = (j & 1) * 2;
                    hmma(s[np2 * 4 + j], ql_, kbh2[p][sel], kbh2[p][sel + 1]);
                }
            }
        }

        // ---- online softmax on fragments ----
        #pragma unroll
        for (int half = 0; half < 2; ++half) {
            float rmax = -1e30f;
            #pragma unroll
            for (int nf = 0; nf < 8; ++nf)
                rmax = fmaxf(rmax, fmaxf(s[nf][half * 2], s[nf][half * 2 + 1]));
            rmax = fmaxf(rmax, __shfl_xor_sync(0xffffffffu, rmax, 1));
            rmax = fmaxf(rmax, __shfl_xor_sync(0xffffffffu, rmax, 2));
            const float mnew = fmaxf(mrow[half], rmax);
            const float corr = __expf(mrow[half] - mnew);
            float rsum = 0.0f;
            #pragma unroll
            for (int nf = 0; nf < 8; ++nf) {
                float p0 = __expf(s[nf][half * 2]     - mnew);
                float p1 = __expf(s[nf][half * 2 + 1] - mnew);
                s[nf][half * 2]     = p0;
                s[nf][half * 2 + 1] = p1;
                rsum += p0 + p1;
            }
            rsum += __shfl_xor_sync(0xffffffffu, rsum, 1);
            rsum += __shfl_xor_sync(0xffffffffu, rsum, 2);
            lrow[half] = lrow[half] * corr + rsum;
            mrow[half] = mnew;
            #pragma unroll
            for (int nf = 0; nf < 8; ++nf) {
                O[nf][half * 2]     *= corr;
                O[nf][half * 2 + 1] *= corr;
            }
        }

        // ---- P @ V (3-MMA split, term-major in np-pairs) ----
        #pragma unroll
        for (int kk = 0; kk < 4; ++kk) {
            uint32_t pah[4], pal[4];
            pah[0] = packsplit(s[2 * kk][0],     s[2 * kk][1],     pal[0]);
            pah[1] = packsplit(s[2 * kk][2],     s[2 * kk][3],     pal[1]);
            pah[2] = packsplit(s[2 * kk + 1][0], s[2 * kk + 1][1], pal[2]);
            pah[3] = packsplit(s[2 * kk + 1][2], s[2 * kk + 1][3], pal[3]);
            #pragma unroll
            for (int np2 = 0; np2 < 2; ++np2) {
                uint32_t vbh2[2][4], vbl2[2][4];
                #pragma unroll
                for (int j = 0; j < 2; ++j) {
                    const int np = np2 * 2 + j;
                    uint32_t n  = np * 16 + (lane & 7) + ((lane >> 4) << 3);
                    uint32_t off = n * 128 + kk * 32 + ((lane >> 3) & 1) * 16;
                    uint32_t sw = swz(off);
                    ldsm_x4(vbh2[j], sb + VH_OFF + sw);
                    ldsm_x4(vbl2[j], sb + VL_OFF + sw);
                }
                #pragma unroll
                for (int j = 0; j < 4; ++j) {
                    const int p = j >> 1, sel = (j & 1) * 2;
                    hmma(O[np2 * 4 + j], pah, vbh2[p][sel], vbh2[p][sel + 1]);
                }
                #pragma unroll
                for (int j = 0; j < 4; ++j) {
                    const int p = j >> 1, sel = (j & 1) * 2;
                    hmma(O[np2 * 4 + j], pal, vbh2[p][sel], vbh2[p][sel + 1]);
                }
                #pragma unroll
                for (int j = 0; j < 4; ++j) {
                    const int p = j >> 1, sel = (j & 1) * 2;
                    hmma(O[np2 * 4 + j], pah, vbl2[p][sel], vbl2[p][sel + 1]);
                }
            }
        }

        __syncthreads();
        if (c + 2 < 32) {
            load_stage((c + 2) * 64, c & 1);
            CP_COMMIT();
            CP_WAIT1();
        } else if (c + 1 < 32) {
            CP_WAIT0();
        }
        __syncthreads();
    }

    // ---- epilogue: normalize, split hi/lo, concat-head layout ----
    const int b = bh >> 4, h = bh & 15;
    const int g = lane >> 2, t = lane & 3;
    #pragma unroll
    for (int half = 0; half < 2; ++half) {
        const float inv = 1.0f / lrow[half];
        const int srow = q0 + mbase + half * 8 + g;
        size_t base = ((size_t)(b * S_ + srow)) * D_ + h * 64;
        #pragma unroll
        for (int nf = 0; nf < 8; ++nf) {
            uint32_t lo, hi = packsplit(O[nf][half * 2] * inv,
                                        O[nf][half * 2 + 1] * inv, lo);
            *reinterpret_cast<uint32_t*>(g_Hh + base + nf * 8 + t * 2) = hi;
            *reinterpret_cast<uint32_t*>(g_Hl + base + nf * 8 + t * 2) = lo;
        }
    }
}

// ---------------- launch ----------------
extern "C" void kernel_launch(void* const* d_in, const int* in_sizes, int n_in,
                              void* d_out, int out_size)
{
    const float* q  = (const float*)d_in[0];
    const float* k  = (const float*)d_in[1];
    const float* v  = (const float*)d_in[2];
    const float* Wq = (const float*)d_in[3];
    const float* Wk = (const float*)d_in[4];
    const float* Wv = (const float*)d_in[5];
    const float* Wo = (const float*)d_in[6];
    float* out = (float*)d_out;

    static bool configured = false;
    if (!configured) {
        cudaFuncSetAttribute(mma_gemm, cudaFuncAttributeMaxDynamicSharedMemorySize, MMA_SMEM);
        cudaFuncSetAttribute(attn_mma, cudaFuncAttributeMaxDynamicSharedMemorySize, ATT_SMEM);
        configured = true;
    }

    __nv_bfloat16 *qh, *ql, *kh, *kl, *vh, *vl;
    __nv_bfloat16 *wqh, *wql, *wkh, *wkl, *wvh, *wvl, *Hh, *Hl;
    cudaGetSymbolAddress((void**)&qh, g_qh);   cudaGetSymbolAddress((void**)&ql, g_ql);
    cudaGetSymbolAddress((void**)&kh, g_kh);   cudaGetSymbolAddress((void**)&kl, g_kl);
    cudaGetSymbolAddress((void**)&vh, g_vh);   cudaGetSymbolAddress((void**)&vl, g_vl);
    cudaGetSymbolAddress((void**)&wqh, g_wqh); cudaGetSymbolAddress((void**)&wql, g_wql);
    cudaGetSymbolAddress((void**)&wkh, g_wkh); cudaGetSymbolAddress((void**)&wkl, g_wkl);
    cudaGetSymbolAddress((void**)&wvh, g_wvh); cudaGetSymbolAddress((void**)&wvl, g_wvl);
    __nv_bfloat16 *woh, *wol;
    cudaGetSymbolAddress((void**)&woh, g_woh); cudaGetSymbolAddress((void**)&wol, g_wol);
    cudaGetSymbolAddress((void**)&Hh, g_Hh);   cudaGetSymbolAddress((void**)&Hl, g_Hl);

    // launches: 3 conversions, then GEMMs (launch idx 5 = Q projection for ncu -s 5)
    conv_in3<<<dim3(8192, 3), 256>>>(q, k, v);
    conv_w3<<<dim3(4096, 3), 256>>>(Wq, Wk, Wv);
    conv_wo<<<4096, 256>>>(Wo);

    dim3 gemm_grid(H_, M_TOT / 128);     // 16 x 64
    mma_gemm<<<gemm_grid, 256, MMA_SMEM>>>(vh, vl, wvh, wvl, nullptr, 2);
    mma_gemm<<<gemm_grid, 256, MMA_SMEM>>>(kh, kl, wkh, wkl, nullptr, 1);
    mma_gemm<<<gemm_grid, 256, MMA_SMEM>>>(qh, ql, wqh, wql, nullptr, 0);

    dim3 attn_grid(S_ / 128, B_ * H_);   // 16 x 64
    attn_mma<<<attn_grid, 256, ATT_SMEM>>>();

    dim3 out_grid(D_ / 64, M_TOT / 128); // 16 x 64
    mma_gemm<<<out_grid, 256, MMA_SMEM>>>(Hh, Hl, woh, wol, out, 3);
}